// round 10
// baseline (speedup 1.0000x reference)
#include <cuda_runtime.h>
#include <cuda_bf16.h>
#include <float.h>
#include <stdint.h>

#define NPTS 2048
#define BATCH 8
#define MTOT (BATCH * NPTS)

// ---------------- scratch (device globals; no runtime allocation) ------------
__device__ float g_G[(size_t)BATCH * NPTS * NPTS];   // 128 MB dist/Gram scratch
__device__ float g_xcat[(size_t)MTOT * 512];
__device__ float g_YZ[(size_t)MTOT * 512];
__device__ float g_xlocal[(size_t)MTOT * 512];
__device__ float g_xemb[(size_t)MTOT * 1024];
__device__ float g_h1[(size_t)MTOT * 256];
__device__ float g_h2[(size_t)MTOT * 256];
__device__ float g_xx[MTOT];
__device__ int   g_idx[MTOT * 20];
__device__ float g_glob[BATCH * 1024];
__device__ float g_gbias[BATCH * 256];
__device__ float g_mean[512];
__device__ __nv_bfloat16 g_Xb[(size_t)MTOT * 1024]; // split [hi|lo] activations
__device__ __nv_bfloat16 g_Xc[(size_t)MTOT * 256];  // centered split (kNN only)
__device__ __nv_bfloat16 g_Wb[(size_t)1024 * 1024]; // split [hi|lo] weights

// ---------------- warp-mma helpers -------------------------------------------
__device__ __forceinline__ uint32_t smem_u32(const void* p) {
    uint32_t a;
    asm("{ .reg .u64 t; cvta.to.shared.u64 t, %1; cvt.u32.u64 %0, t; }"
        : "=r"(a) : "l"(p));
    return a;
}
__device__ __forceinline__ void ldsm_x4(uint32_t* r, uint32_t addr) {
    asm volatile("ldmatrix.sync.aligned.m8n8.x4.shared.b16 {%0,%1,%2,%3}, [%4];"
                 : "=r"(r[0]), "=r"(r[1]), "=r"(r[2]), "=r"(r[3]) : "r"(addr));
}
__device__ __forceinline__ void mma16816(float* c, const uint32_t* a,
                                         uint32_t b0, uint32_t b1) {
    asm volatile(
        "mma.sync.aligned.m16n8k16.row.col.f32.bf16.bf16.f32 "
        "{%0,%1,%2,%3}, {%4,%5,%6,%7}, {%8,%9}, {%0,%1,%2,%3};"
        : "+f"(c[0]), "+f"(c[1]), "+f"(c[2]), "+f"(c[3])
        : "r"(a[0]), "r"(a[1]), "r"(a[2]), "r"(a[3]), "r"(b0), "r"(b1));
}
#define CPA16(dst, src) \
    asm volatile("cp.async.cg.shared.global [%0], [%1], 16;" :: "r"(dst), "l"(src))
#define CPA_COMMIT() asm volatile("cp.async.commit_group;" ::: "memory")

#define PITCH 40   // smem row pitch in bf16 (80B: conflict-free ldmatrix)

// ---------------- split-bf16 tensor GEMM: out[m,o] = sum_c X[m,c]*W[o,c] -----
// A, B are split buffers [hi(C) | lo(C)] per row; accumulate
// hi*hi + hi*lo + lo*hi in fp32 via mma.sync.
// PIPE=true requires C%32==0, lda%8==0, ldb%8==0 (cp.async 2-stage pipeline).
// MODE 0: raw  1: lrelu(s*v+t)  2: lrelu(s*(v+gadd[b,o])+t)  3: v+t[o]
template <int MODE, bool PIPE>
__global__ void __launch_bounds__(128) gemm_mma(
    const __nv_bfloat16* __restrict__ Ab, int lda, long bsA,
    const __nv_bfloat16* __restrict__ Bb, int ldb, long bsB,
    float* __restrict__ Ob, int ldo, long bsO,
    int M, int C, int O,
    const float* __restrict__ s, const float* __restrict__ t,
    const float* __restrict__ gadd)
{
    __shared__ __align__(16) __nv_bfloat16 sAh[2][128 * PITCH];
    __shared__ __align__(16) __nv_bfloat16 sAl[2][128 * PITCH];
    __shared__ __align__(16) __nv_bfloat16 sBh[2][64 * PITCH];
    __shared__ __align__(16) __nv_bfloat16 sBl[2][64 * PITCH];

    const __nv_bfloat16* A = Ab + (long)blockIdx.z * bsA;
    const __nv_bfloat16* B = Bb + (long)blockIdx.z * bsB;
    float* Out = Ob + (long)blockIdx.z * bsO;
    const int m0 = blockIdx.y * 128, o0 = blockIdx.x * 64;
    const int tid = threadIdx.x, lane = tid & 31, w = tid >> 5;
    const __nv_bfloat16 zb = __float2bfloat16(0.0f);

    float acc[2][8][4];
#pragma unroll
    for (int i = 0; i < 2; i++)
#pragma unroll
        for (int j = 0; j < 8; j++)
#pragma unroll
            for (int q = 0; q < 4; q++) acc[i][j][q] = 0.f;

    const int nch = (C + 31) >> 5;

    if (PIPE) {
        // per-thread cp.async staging addresses
        const long ra = (long)(m0 + tid) * lda;
        const uint32_t dAh = smem_u32(sAh) + tid * (PITCH * 2);
        const uint32_t dAl = smem_u32(sAl) + tid * (PITCH * 2);
        const uint32_t dBh = smem_u32(sBh) + tid * (PITCH * 2);
        const uint32_t dBl = smem_u32(sBl) + tid * (PITCH * 2);
        const long rb = (tid < 64) ? (long)(o0 + tid) * ldb : 0;

        // prologue: chunk 0 -> buf 0
        {
            const __nv_bfloat16* ph = A + ra;
            const __nv_bfloat16* pl = A + ra + C;
#pragma unroll
            for (int q = 0; q < 4; q++) {
                CPA16(dAh + q * 16, ph + q * 8);
                CPA16(dAl + q * 16, pl + q * 8);
            }
            if (tid < 64) {
                const __nv_bfloat16* qh = B + rb;
                const __nv_bfloat16* ql = B + rb + C;
#pragma unroll
                for (int q = 0; q < 4; q++) {
                    CPA16(dBh + q * 16, qh + q * 8);
                    CPA16(dBl + q * 16, ql + q * 8);
                }
            }
            CPA_COMMIT();
        }

        for (int cc = 0; cc < nch; cc++) {
            if (cc + 1 < nch) {
                const int kb = (cc + 1) * 32;
                const uint32_t bo = ((cc + 1) & 1) * (128 * PITCH * 2);
                const uint32_t bo2 = ((cc + 1) & 1) * (64 * PITCH * 2);
                const __nv_bfloat16* ph = A + ra + kb;
                const __nv_bfloat16* pl = A + ra + C + kb;
#pragma unroll
                for (int q = 0; q < 4; q++) {
                    CPA16(dAh + bo + q * 16, ph + q * 8);
                    CPA16(dAl + bo + q * 16, pl + q * 8);
                }
                if (tid < 64) {
                    const __nv_bfloat16* qh = B + rb + kb;
                    const __nv_bfloat16* ql = B + rb + C + kb;
#pragma unroll
                    for (int q = 0; q < 4; q++) {
                        CPA16(dBh + bo2 + q * 16, qh + q * 8);
                        CPA16(dBl + bo2 + q * 16, ql + q * 8);
                    }
                }
                CPA_COMMIT();
                asm volatile("cp.async.wait_group 1;" ::: "memory");
            } else {
                asm volatile("cp.async.wait_group 0;" ::: "memory");
            }
            __syncthreads();

            const int buf = cc & 1;
            const uint32_t uAhi = smem_u32(sAh[buf]);
            const uint32_t uAlo = smem_u32(sAl[buf]);
            const uint32_t uBhi = smem_u32(sBh[buf]);
            const uint32_t uBlo = smem_u32(sBl[buf]);
#pragma unroll
            for (int ks = 0; ks < 2; ks++) {
                const int k0 = ks * 16;
                uint32_t ah[2][4], al[2][4], bh[4][4], bl[4][4];
                const int arow = lane & 15;
                const int acol = k0 + ((lane >> 4) << 3);
#pragma unroll
                for (int i = 0; i < 2; i++) {
                    uint32_t off = ((w * 32 + i * 16 + arow) * PITCH + acol) * 2;
                    ldsm_x4(ah[i], uAhi + off);
                    ldsm_x4(al[i], uAlo + off);
                }
                const int seg = lane >> 3;
                const int brow = (lane & 7) + ((seg & 2) << 2);
                const int bcol = k0 + ((seg & 1) << 3);
#pragma unroll
                for (int jp = 0; jp < 4; jp++) {
                    uint32_t off = ((jp * 16 + brow) * PITCH + bcol) * 2;
                    ldsm_x4(bh[jp], uBhi + off);
                    ldsm_x4(bl[jp], uBlo + off);
                }
#pragma unroll
                for (int i = 0; i < 2; i++)
#pragma unroll
                    for (int jp = 0; jp < 4; jp++) {
                        mma16816(acc[i][2 * jp],     ah[i], bh[jp][0], bh[jp][1]);
                        mma16816(acc[i][2 * jp + 1], ah[i], bh[jp][2], bh[jp][3]);
                        mma16816(acc[i][2 * jp],     ah[i], bl[jp][0], bl[jp][1]);
                        mma16816(acc[i][2 * jp + 1], ah[i], bl[jp][2], bl[jp][3]);
                        mma16816(acc[i][2 * jp],     al[i], bh[jp][0], bh[jp][1]);
                        mma16816(acc[i][2 * jp + 1], al[i], bh[jp][2], bh[jp][3]);
                    }
            }
            __syncthreads();
        }
    } else {
        // legacy scalar path (C=3 layer-1 YZ): single buffer, synchronous
        for (int cc = 0; cc < nch; cc++) {
            const int kb = cc * 32;
            int vc = C - kb; if (vc > 32) vc = 32;
            __syncthreads();
            {
                const int r = tid;
                const long ra = (long)(m0 + r) * lda;
                for (int j = 0; j < 32; j++) {
                    bool ok = (j < vc);
                    sAh[0][r * PITCH + j] = ok ? A[ra + kb + j] : zb;
                    sAl[0][r * PITCH + j] = ok ? A[ra + C + kb + j] : zb;
                }
            }
            if (tid < 64) {
                const int r = tid;
                const int o = o0 + r;
                for (int j = 0; j < 32; j++) {
                    bool ok = (o < O) && (j < vc);
                    sBh[0][r * PITCH + j] = ok ? B[(long)o * ldb + kb + j] : zb;
                    sBl[0][r * PITCH + j] = ok ? B[(long)o * ldb + C + kb + j] : zb;
                }
            }
            __syncthreads();
            const uint32_t uAhi = smem_u32(sAh[0]);
            const uint32_t uAlo = smem_u32(sAl[0]);
            const uint32_t uBhi = smem_u32(sBh[0]);
            const uint32_t uBlo = smem_u32(sBl[0]);
#pragma unroll
            for (int ks = 0; ks < 2; ks++) {
                const int k0 = ks * 16;
                uint32_t ah[2][4], al[2][4], bh[4][4], bl[4][4];
                const int arow = lane & 15;
                const int acol = k0 + ((lane >> 4) << 3);
#pragma unroll
                for (int i = 0; i < 2; i++) {
                    uint32_t off = ((w * 32 + i * 16 + arow) * PITCH + acol) * 2;
                    ldsm_x4(ah[i], uAhi + off);
                    ldsm_x4(al[i], uAlo + off);
                }
                const int seg = lane >> 3;
                const int brow = (lane & 7) + ((seg & 2) << 2);
                const int bcol = k0 + ((seg & 1) << 3);
#pragma unroll
                for (int jp = 0; jp < 4; jp++) {
                    uint32_t off = ((jp * 16 + brow) * PITCH + bcol) * 2;
                    ldsm_x4(bh[jp], uBhi + off);
                    ldsm_x4(bl[jp], uBlo + off);
                }
#pragma unroll
                for (int i = 0; i < 2; i++)
#pragma unroll
                    for (int jp = 0; jp < 4; jp++) {
                        mma16816(acc[i][2 * jp],     ah[i], bh[jp][0], bh[jp][1]);
                        mma16816(acc[i][2 * jp + 1], ah[i], bh[jp][2], bh[jp][3]);
                        mma16816(acc[i][2 * jp],     ah[i], bl[jp][0], bl[jp][1]);
                        mma16816(acc[i][2 * jp + 1], ah[i], bl[jp][2], bl[jp][3]);
                        mma16816(acc[i][2 * jp],     al[i], bh[jp][0], bh[jp][1]);
                        mma16816(acc[i][2 * jp + 1], al[i], bh[jp][2], bh[jp][3]);
                    }
            }
        }
    }

    // epilogue: fragment layout -> global, fused activation
    const int qrow = lane >> 2, qcol = (lane & 3) * 2;
#pragma unroll
    for (int i = 0; i < 2; i++) {
        const int mA = m0 + w * 32 + i * 16 + qrow;
#pragma unroll
        for (int j = 0; j < 8; j++) {
            const int o = o0 + j * 8 + qcol;
#pragma unroll
            for (int q = 0; q < 4; q++) {
                const int m = mA + ((q >> 1) ? 8 : 0);
                const int oo = o + (q & 1);
                if (oo >= O) continue;
                float v = acc[i][j][q];
                if (MODE == 1) { v = s[oo] * v + t[oo]; v = v >= 0.f ? v : 0.2f * v; }
                else if (MODE == 2) {
                    v = s[oo] * (v + gadd[(m >> 11) * O + oo]) + t[oo];
                    v = v >= 0.f ? v : 0.2f * v;
                }
                else if (MODE == 3) { v = v + t[oo]; }
                Out[(long)m * ldo + oo] = v;
            }
        }
    }
}

// ---------------- column means over MTOT rows --------------------------------
__global__ void __launch_bounds__(256) colmean_kernel(
    const float* __restrict__ X, int ldx, float* __restrict__ mean)
{
    __shared__ float sh[8];
    const int c = blockIdx.x;
    float a = 0.f;
    for (int m = threadIdx.x; m < MTOT; m += 256) a += X[(long)m * ldx + c];
#pragma unroll
    for (int off = 16; off > 0; off >>= 1) a += __shfl_down_sync(0xFFFFFFFFu, a, off);
    if ((threadIdx.x & 31) == 0) sh[threadIdx.x >> 5] = a;
    __syncthreads();
    if (threadIdx.x == 0) {
        float tot = 0.f;
#pragma unroll
        for (int i = 0; i < 8; i++) tot += sh[i];
        mean[c] = tot * (1.f / MTOT);
    }
}

// ---------------- fp32 -> split bf16 [hi|lo] ---------------------------------
__global__ void conv_split(const float* __restrict__ X, int ldx, int C, int Mrows,
                           __nv_bfloat16* __restrict__ Y)
{
    long i = (long)blockIdx.x * blockDim.x + threadIdx.x;
    long tot = (long)Mrows * C;
    if (i >= tot) return;
    int m = (int)(i / C), c = (int)(i - (long)m * C);
    float x = X[(long)m * ldx + c];
    __nv_bfloat16 h = __float2bfloat16(x);
    float lo = x - __bfloat162float(h);
    Y[(long)m * 2 * C + c] = h;
    Y[(long)m * 2 * C + C + c] = __float2bfloat16(lo);
}

// ---------------- fp32 -> centered split bf16 (for kNN Gram) -----------------
__global__ void conv_split_center(const float* __restrict__ X, int ldx, int C,
                                  const float* __restrict__ mean,
                                  __nv_bfloat16* __restrict__ Y)
{
    long i = (long)blockIdx.x * blockDim.x + threadIdx.x;
    long tot = (long)MTOT * C;
    if (i >= tot) return;
    int m = (int)(i / C), c = (int)(i - (long)m * C);
    float x = X[(long)m * ldx + c] - mean[c];
    __nv_bfloat16 h = __float2bfloat16(x);
    float lo = x - __bfloat162float(h);
    Y[(long)m * 2 * C + c] = h;
    Y[(long)m * 2 * C + C + c] = __float2bfloat16(lo);
}

// ---------------- [W1 ; W2-W1] directly to split bf16 ------------------------
__global__ void prep_wc_split(const float* __restrict__ w,
                              __nv_bfloat16* __restrict__ wcb, int O, int C)
{
    int i = blockIdx.x * blockDim.x + threadIdx.x;
    if (i >= O * C) return;
    int o = i / C, c = i - o * C;
    float w1 = w[(long)o * 2 * C + c];
    float w2 = w[(long)o * 2 * C + C + c];
    __nv_bfloat16 h1b = __float2bfloat16(w1);
    wcb[(long)o * 2 * C + c] = h1b;
    wcb[(long)o * 2 * C + C + c] = __float2bfloat16(w1 - __bfloat162float(h1b));
    float d = w2 - w1;
    __nv_bfloat16 h2b = __float2bfloat16(d);
    wcb[(long)(O + o) * 2 * C + c] = h2b;
    wcb[(long)(O + o) * 2 * C + C + c] = __float2bfloat16(d - __bfloat162float(h2b));
}

// ---------------- centered squared row norms ---------------------------------
__global__ void rownorm_center(const float* __restrict__ X, int ldx, int C,
                               const float* __restrict__ mean,
                               float* __restrict__ xx)
{
    int m = blockIdx.x * blockDim.x + threadIdx.x;
    if (m >= MTOT) return;
    const float* p = X + (long)m * ldx;
    float a = 0.f;
    for (int c = 0; c < C; c++) { float d = p[c] - mean[c]; a += d * d; }
    xx[m] = a;
}

// ---------------- layer-1 fused exact kNN (xyz in smem) ----------------------
__global__ void __launch_bounds__(128) topk_xyz(
    const float* __restrict__ xyz, int* __restrict__ idxout)
{
    __shared__ float sx[NPTS], sy[NPTS], sz[NPTS];
    __shared__ float wv[4];
    __shared__ int   wi[4];
    __shared__ int   gsh;

    const int row = blockIdx.x;
    const int b = row >> 11, n = row & 2047;
    const float* xb = xyz + (long)b * NPTS * 3;
    const int tid = threadIdx.x;
    const int lane = tid & 31, wrp = tid >> 5;

    for (int j = tid; j < NPTS; j += 128) {
        sx[j] = xb[j * 3];
        sy[j] = xb[j * 3 + 1];
        sz[j] = xb[j * 3 + 2];
    }
    __syncthreads();
    const float xi = sx[n], yi = sy[n], zi = sz[n];

    float v[16];
#pragma unroll
    for (int i = 0; i < 16; i++) {
        int j = i * 128 + tid;
        float dx = sx[j] - xi, dy = sy[j] - yi, dz = sz[j] - zi;
        v[i] = dx * dx + dy * dy + dz * dz;
    }
    float mv = v[0];
    int ms = 0;
#pragma unroll
    for (int i = 1; i < 16; i++)
        if (v[i] < mv) { mv = v[i]; ms = i; }

    for (int itk = 0; itk < 20; itk++) {
        float bv = mv;
        int bidx = ms * 128 + tid;
#pragma unroll
        for (int off = 16; off > 0; off >>= 1) {
            float ov = __shfl_down_sync(0xFFFFFFFFu, bv, off);
            int oi = __shfl_down_sync(0xFFFFFFFFu, bidx, off);
            if (ov < bv || (ov == bv && oi < bidx)) { bv = ov; bidx = oi; }
        }
        if (lane == 0) { wv[wrp] = bv; wi[wrp] = bidx; }
        __syncthreads();
        if (tid == 0) {
            bv = wv[0]; bidx = wi[0];
#pragma unroll
            for (int ww = 1; ww < 4; ww++)
                if (wv[ww] < bv || (wv[ww] == bv && wi[ww] < bidx)) { bv = wv[ww]; bidx = wi[ww]; }
            idxout[row * 20 + itk] = bidx;
            gsh = bidx;
        }
        __syncthreads();
        const int gb = gsh;
        if ((gb & 127) == tid) {
            v[gb >> 7] = FLT_MAX;
            mv = v[0]; ms = 0;
#pragma unroll
            for (int i = 1; i < 16; i++)
                if (v[i] < mv) { mv = v[i]; ms = i; }
        }
        __syncthreads();
    }
}

// ---------------- top-20 smallest of d_j = xx_i + xx_j - 2*G[i,j] ------------
__global__ void __launch_bounds__(128) topk_kernel(
    const float* __restrict__ G, const float* __restrict__ xx,
    int* __restrict__ idxout)
{
    __shared__ float wv[4];
    __shared__ int   wi[4];
    __shared__ int   gsh;

    const int row = blockIdx.x;
    const int b = row >> 11;
    const float* g = G + (long)row * NPTS;
    const float* xxb = xx + (b << 11);
    const float xi = xx[row];
    const int tid = threadIdx.x;
    const int lane = tid & 31, wrp = tid >> 5;

    float v[16];
#pragma unroll
    for (int i = 0; i < 16; i++) {
        int j = i * 128 + tid;
        v[i] = xi + xxb[j] - 2.f * g[j];
    }
    float mv = v[0];
    int ms = 0;
#pragma unroll
    for (int i = 1; i < 16; i++)
        if (v[i] < mv) { mv = v[i]; ms = i; }

    for (int itk = 0; itk < 20; itk++) {
        float bv = mv;
        int bidx = ms * 128 + tid;
#pragma unroll
        for (int off = 16; off > 0; off >>= 1) {
            float ov = __shfl_down_sync(0xFFFFFFFFu, bv, off);
            int oi = __shfl_down_sync(0xFFFFFFFFu, bidx, off);
            if (ov < bv || (ov == bv && oi < bidx)) { bv = ov; bidx = oi; }
        }
        if (lane == 0) { wv[wrp] = bv; wi[wrp] = bidx; }
        __syncthreads();
        if (tid == 0) {
            bv = wv[0]; bidx = wi[0];
#pragma unroll
            for (int ww = 1; ww < 4; ww++)
                if (wv[ww] < bv || (wv[ww] == bv && wi[ww] < bidx)) { bv = wv[ww]; bidx = wi[ww]; }
            idxout[row * 20 + itk] = bidx;
            gsh = bidx;
        }
        __syncthreads();
        const int gb = gsh;
        if ((gb & 127) == tid) {
            v[gb >> 7] = FLT_MAX;
            mv = v[0]; ms = 0;
#pragma unroll
            for (int i = 1; i < 16; i++)
                if (v[i] < mv) { mv = v[i]; ms = i; }
        }
        __syncthreads();
    }
}

// ---------------- gather-max over k neighbors + epilogue ---------------------
__global__ void __launch_bounds__(128) edge_max_kernel(
    const float* __restrict__ YZ, int ldyz,
    const int* __restrict__ idx,
    const float* __restrict__ s,
    const float* __restrict__ t,
    float* __restrict__ out, int ldo, int O)
{
    __shared__ int nb[20];
    int bn = blockIdx.x;
    int bbase = (bn >> 11) << 11;
    if (threadIdx.x < 20) nb[threadIdx.x] = idx[bn * 20 + threadIdx.x];
    __syncthreads();
    for (int o = threadIdx.x; o < O; o += 128) {
        float z = YZ[(long)bn * ldyz + O + o];
        float m = -FLT_MAX;
#pragma unroll
        for (int kk = 0; kk < 20; kk++) {
            float y = YZ[(long)(bbase + nb[kk]) * ldyz + o];
            m = fmaxf(m, y);
        }
        float v = s[o] * (m + z) + t[o];
        out[(long)bn * ldo + o] = v >= 0.f ? v : 0.2f * v;
    }
}

// ---------------- global max over N (coalesced) ------------------------------
__global__ void __launch_bounds__(256) maxreduce_kernel(
    const float* __restrict__ xemb, float* __restrict__ glob)
{
    __shared__ float sh[8][33];
    const int lane = threadIdx.x & 31, grp = threadIdx.x >> 5;
    const int o = blockIdx.x * 32 + lane;
    const int b = blockIdx.y;
    const float* p = xemb + (long)b * NPTS * 1024 + o;
    float m = -FLT_MAX;
    for (int n = grp; n < NPTS; n += 8) m = fmaxf(m, p[(long)n * 1024]);
    sh[grp][lane] = m;
    __syncthreads();
    if (grp == 0) {
#pragma unroll
        for (int r = 1; r < 8; r++) m = fmaxf(m, sh[r][lane]);
        glob[b * 1024 + o] = m;
    }
}

// ---------------- per-batch global-feature bias for h1 -----------------------
__global__ void gbias_kernel(const float* __restrict__ h1w,
                             const float* __restrict__ glob,
                             float* __restrict__ gb)
{
    __shared__ float gsh[1024];
    int b = blockIdx.x, o = threadIdx.x;
    for (int c = threadIdx.x; c < 1024; c += 256) gsh[c] = glob[b * 1024 + c];
    __syncthreads();
    const float* wr = h1w + (long)o * 1536 + 512;
    float acc = 0.f;
    for (int c = 0; c < 1024; c++) acc += gsh[c] * wr[c];
    gb[b * 256 + o] = acc;
}

// ---------------- host orchestration -----------------------------------------
static inline dim3 tgrid(int M, int O, int Z) {
    return dim3((O + 63) / 64, (M + 127) / 128, Z);
}
static inline int cgrid(long n) { return (int)((n + 255) / 256); }

// layers 2-4: centered split-bf16 Gram kNN + split-bf16 YZ GEMM
static void run_edge_layer_tc(const float* X, int ldx, int C, int O,
                              const float* w, const float* s, const float* t,
                              float* pG, float* pxx, int* pidx, float* pmean,
                              __nv_bfloat16* pXb, __nv_bfloat16* pXc,
                              __nv_bfloat16* pWb, float* pYZ, float* outcol)
{
    colmean_kernel<<<C, 256>>>(X, ldx, pmean);
    conv_split_center<<<cgrid((long)MTOT * C), 256>>>(X, ldx, C, pmean, pXc);
    rownorm_center<<<cgrid(MTOT), 256>>>(X, ldx, C, pmean, pxx);
    conv_split<<<cgrid((long)MTOT * C), 256>>>(X, ldx, C, MTOT, pXb);
    prep_wc_split<<<cgrid(O * C), 256>>>(w, pWb, O, C);
    gemm_mma<0, true><<<tgrid(NPTS, NPTS, BATCH), 128>>>(
        pXc, 2 * C, (long)NPTS * 2 * C, pXc, 2 * C, (long)NPTS * 2 * C,
        pG, NPTS, (long)NPTS * NPTS, NPTS, C, NPTS, nullptr, nullptr, nullptr);
    topk_kernel<<<MTOT, 128>>>(pG, pxx, pidx);
    gemm_mma<0, true><<<tgrid(MTOT, 2 * O, 1), 128>>>(
        pXb, 2 * C, 0L, pWb, 2 * C, 0L, pYZ, 2 * O, 0L,
        MTOT, C, 2 * O, nullptr, nullptr, nullptr);
    edge_max_kernel<<<MTOT, 128>>>(pYZ, 2 * O, pidx, s, t, outcol, 512, O);
}

extern "C" void kernel_launch(void* const* d_in, const int* in_sizes, int n_in,
                              void* d_out, int out_size)
{
    const float* xyz    = (const float*)d_in[0];
    const float* ec1_w  = (const float*)d_in[1];
    const float* ec1_s  = (const float*)d_in[2];
    const float* ec1_t  = (const float*)d_in[3];
    const float* ec2_w  = (const float*)d_in[4];
    const float* ec2_s  = (const float*)d_in[5];
    const float* ec2_t  = (const float*)d_in[6];
    const float* ec3_w  = (const float*)d_in[7];
    const float* ec3_s  = (const float*)d_in[8];
    const float* ec3_t  = (const float*)d_in[9];
    const float* ec4_w  = (const float*)d_in[10];
    const float* ec4_s  = (const float*)d_in[11];
    const float* ec4_t  = (const float*)d_in[12];
    const float* fuse_w = (const float*)d_in[13];
    const float* fuse_s = (const float*)d_in[14];
    const float* fuse_t = (const float*)d_in[15];
    const float* emb_w  = (const float*)d_in[16];
    const float* emb_s  = (const float*)d_in[17];
    const float* emb_t  = (const float*)d_in[18];
    const float* h1_w   = (const float*)d_in[19];
    const float* h1_s   = (const float*)d_in[20];
    const float* h1_t   = (const float*)d_in[21];
    const float* h2_w   = (const float*)d_in[22];
    const float* h2_s   = (const float*)d_in[23];
    const float* h2_t   = (const float*)d_in[24];
    const float* h3_w   = (const float*)d_in[25];
    const float* h3_b   = (const float*)d_in[26];
    float* out = (float*)d_out;

    float *pG, *pxcat, *pYZ, *pxloc, *pxemb, *ph1, *ph2, *pxx, *pglob, *pgb, *pmean;
    __nv_bfloat16 *pXb, *pXc, *pWb;
    int* pidx;
    cudaGetSymbolAddress((void**)&pG, g_G);
    cudaGetSymbolAddress((void**)&pxcat, g_xcat);
    cudaGetSymbolAddress((void**)&pYZ, g_YZ);
    cudaGetSymbolAddress((void**)&pxloc, g_xlocal);
    cudaGetSymbolAddress((void**)&pxemb, g_xemb);
    cudaGetSymbolAddress((void**)&ph1, g_h1);
    cudaGetSymbolAddress((void**)&ph2, g_h2);
    cudaGetSymbolAddress((void**)&pxx, g_xx);
    cudaGetSymbolAddress((void**)&pglob, g_glob);
    cudaGetSymbolAddress((void**)&pgb, g_gbias);
    cudaGetSymbolAddress((void**)&pmean, g_mean);
    cudaGetSymbolAddress((void**)&pXb, g_Xb);
    cudaGetSymbolAddress((void**)&pXc, g_Xc);
    cudaGetSymbolAddress((void**)&pWb, g_Wb);
    cudaGetSymbolAddress((void**)&pidx, g_idx);

    // ---- layer 1: exact fused kNN on xyz, split-bf16 YZ (C=3, legacy path) --
    conv_split<<<cgrid((long)MTOT * 3), 256>>>(xyz, 3, 3, MTOT, pXb);
    prep_wc_split<<<cgrid(64 * 3), 256>>>(ec1_w, pWb, 64, 3);
    gemm_mma<0, false><<<tgrid(MTOT, 128, 1), 128>>>(
        pXb, 6, 0L, pWb, 6, 0L, pYZ, 128, 0L,
        MTOT, 3, 128, nullptr, nullptr, nullptr);
    topk_xyz<<<MTOT, 128>>>(xyz, pidx);
    edge_max_kernel<<<MTOT, 128>>>(pYZ, 128, pidx, ec1_s, ec1_t, pxcat + 0, 512, 64);

    // ---- layers 2-4 ----
    run_edge_layer_tc(pxcat + 0,   512, 64,  64,  ec2_w, ec2_s, ec2_t,
                      pG, pxx, pidx, pmean, pXb, pXc, pWb, pYZ, pxcat + 64);
    run_edge_layer_tc(pxcat + 64,  512, 64,  128, ec3_w, ec3_s, ec3_t,
                      pG, pxx, pidx, pmean, pXb, pXc, pWb, pYZ, pxcat + 128);
    run_edge_layer_tc(pxcat + 128, 512, 128, 256, ec4_w, ec4_s, ec4_t,
                      pG, pxx, pidx, pmean, pXb, pXc, pWb, pYZ, pxcat + 256);

    // fuse: (16384,512) -> 512, lrelu
    conv_split<<<cgrid((long)MTOT * 512), 256>>>(pxcat, 512, 512, MTOT, pXb);
    conv_split<<<cgrid(512L * 512), 256>>>(fuse_w, 512, 512, 512, pWb);
    gemm_mma<1, true><<<tgrid(MTOT, 512, 1), 128>>>(
        pXb, 1024, 0L, pWb, 1024, 0L, pxloc, 512, 0L,
        MTOT, 512, 512, fuse_s, fuse_t, nullptr);
    // emb: 512 -> 1024, lrelu
    conv_split<<<cgrid((long)MTOT * 512), 256>>>(pxloc, 512, 512, MTOT, pXb);
    conv_split<<<cgrid(1024L * 512), 256>>>(emb_w, 512, 512, 1024, pWb);
    gemm_mma<1, true><<<tgrid(MTOT, 1024, 1), 128>>>(
        pXb, 1024, 0L, pWb, 1024, 0L, pxemb, 1024, 0L,
        MTOT, 512, 1024, emb_s, emb_t, nullptr);
    // global max over N + per-batch bias via h1_w[:,512:]
    maxreduce_kernel<<<dim3(32, BATCH), 256>>>(pxemb, pglob);
    gbias_kernel<<<BATCH, 256>>>(h1_w, pglob, pgb);
    // h1: 512 -> 256 with per-batch gadd, lrelu (xloc split still in pXb)
    conv_split<<<cgrid(256L * 512), 256>>>(h1_w, 1536, 512, 256, pWb);
    gemm_mma<2, true><<<tgrid(MTOT, 256, 1), 128>>>(
        pXb, 1024, 0L, pWb, 1024, 0L, ph1, 256, 0L,
        MTOT, 512, 256, h1_s, h1_t, pgb);
    // h2: 256 -> 256, lrelu
    conv_split<<<cgrid((long)MTOT * 256), 256>>>(ph1, 256, 256, MTOT, pXb);
    conv_split<<<cgrid(256L * 256), 256>>>(h2_w, 256, 256, 256, pWb);
    gemm_mma<1, true><<<tgrid(MTOT, 256, 1), 128>>>(
        pXb, 512, 0L, pWb, 512, 0L, ph2, 256, 0L,
        MTOT, 256, 256, h2_s, h2_t, nullptr);
    // h3: 256 -> 13, +bias -> d_out
    conv_split<<<cgrid((long)MTOT * 256), 256>>>(ph2, 256, 256, MTOT, pXb);
    conv_split<<<cgrid(13L * 256), 256>>>(h3_w, 256, 256, 13, pWb);
    gemm_mma<3, true><<<tgrid(MTOT, 13, 1), 128>>>(
        pXb, 512, 0L, pWb, 512, 0L, out, 13, 0L,
        MTOT, 256, 13, nullptr, h3_b, nullptr);
}

// round 11
// speedup vs baseline: 1.3754x; 1.3754x over previous
#include <cuda_runtime.h>
#include <cuda_bf16.h>
#include <float.h>
#include <stdint.h>

#define NPTS 2048
#define BATCH 8
#define MTOT (BATCH * NPTS)

// ---------------- scratch (device globals; no runtime allocation) ------------
__device__ float g_G[(size_t)BATCH * NPTS * NPTS];   // 128 MB dist/Gram scratch
__device__ float g_xcat[(size_t)MTOT * 512];
__device__ float g_YZ[(size_t)MTOT * 512];
__device__ float g_xlocal[(size_t)MTOT * 512];
__device__ float g_xemb[(size_t)MTOT * 1024];
__device__ float g_h1[(size_t)MTOT * 256];
__device__ float g_h2[(size_t)MTOT * 256];
__device__ float g_xx[MTOT];
__device__ int   g_idx[MTOT * 20];
__device__ float g_glob[BATCH * 1024];
__device__ float g_gbias[BATCH * 256];
__device__ float g_mean[512];
__device__ float g_msum[64 * 512];
__device__ __nv_bfloat16 g_Xb[(size_t)MTOT * 1024];  // split scratch A
__device__ __nv_bfloat16 g_Xb2[(size_t)MTOT * 1024]; // split scratch B
__device__ __nv_bfloat16 g_Xc[(size_t)MTOT * 256];   // centered split (kNN)
__device__ __nv_bfloat16 g_Wb[(size_t)1024 * 1024];  // split weights

// ---------------- warp-mma helpers -------------------------------------------
__device__ __forceinline__ uint32_t smem_u32(const void* p) {
    uint32_t a;
    asm("{ .reg .u64 t; cvta.to.shared.u64 t, %1; cvt.u32.u64 %0, t; }"
        : "=r"(a) : "l"(p));
    return a;
}
__device__ __forceinline__ void ldsm_x4(uint32_t* r, uint32_t addr) {
    asm volatile("ldmatrix.sync.aligned.m8n8.x4.shared.b16 {%0,%1,%2,%3}, [%4];"
                 : "=r"(r[0]), "=r"(r[1]), "=r"(r[2]), "=r"(r[3]) : "r"(addr));
}
__device__ __forceinline__ void mma16816(float* c, const uint32_t* a,
                                         uint32_t b0, uint32_t b1) {
    asm volatile(
        "mma.sync.aligned.m16n8k16.row.col.f32.bf16.bf16.f32 "
        "{%0,%1,%2,%3}, {%4,%5,%6,%7}, {%8,%9}, {%0,%1,%2,%3};"
        : "+f"(c[0]), "+f"(c[1]), "+f"(c[2]), "+f"(c[3])
        : "r"(a[0]), "r"(a[1]), "r"(a[2]), "r"(a[3]), "r"(b0), "r"(b1));
}

#define PITCH 40   // smem row pitch in bf16 (80B: conflict-free ldmatrix)

// ---------------- split-bf16 tensor GEMM: out[m,o] = sum_c X[m,c]*W[o,c] -----
// A, B are split buffers [hi(C) | lo(C)] per row; accumulate
// hi*hi + hi*lo + lo*hi in fp32 via mma.sync. (R7 synchronous staging.)
// Optional So/ldso: also emit split-bf16 [hi|lo] of the activated output.
// MODE 0: raw  1: lrelu(s*v+t)  2: lrelu(s*(v+gadd[b,o])+t)  3: v+t[o]
template <int MODE>
__global__ void __launch_bounds__(128) gemm_mma(
    const __nv_bfloat16* __restrict__ Ab, int lda, long bsA,
    const __nv_bfloat16* __restrict__ Bb, int ldb, long bsB,
    float* __restrict__ Ob, int ldo, long bsO,
    int M, int C, int O,
    const float* __restrict__ s, const float* __restrict__ t,
    const float* __restrict__ gadd,
    __nv_bfloat16* __restrict__ So, int ldso)
{
    __shared__ __align__(16) __nv_bfloat16 sAhi[128 * PITCH];
    __shared__ __align__(16) __nv_bfloat16 sAlo[128 * PITCH];
    __shared__ __align__(16) __nv_bfloat16 sBhi[64 * PITCH];
    __shared__ __align__(16) __nv_bfloat16 sBlo[64 * PITCH];

    const __nv_bfloat16* A = Ab + (long)blockIdx.z * bsA;
    const __nv_bfloat16* B = Bb + (long)blockIdx.z * bsB;
    float* Out = Ob + (long)blockIdx.z * bsO;
    const int m0 = blockIdx.y * 128, o0 = blockIdx.x * 64;
    const int tid = threadIdx.x, lane = tid & 31, w = tid >> 5;
    const __nv_bfloat16 zb = __float2bfloat16(0.0f);

    const uint32_t uAhi = smem_u32(sAhi), uAlo = smem_u32(sAlo);
    const uint32_t uBhi = smem_u32(sBhi), uBlo = smem_u32(sBlo);

    float acc[2][8][4];
#pragma unroll
    for (int i = 0; i < 2; i++)
#pragma unroll
        for (int j = 0; j < 8; j++)
#pragma unroll
            for (int q = 0; q < 4; q++) acc[i][j][q] = 0.f;

    const int nch = (C + 31) >> 5;
    const bool fastv = ((lda & 7) == 0) && ((ldb & 7) == 0) && ((C & 7) == 0);

    for (int cc = 0; cc < nch; cc++) {
        const int kb = cc * 32;
        int vc = C - kb; if (vc > 32) vc = 32;
        const bool fast = fastv && (vc == 32);

        __syncthreads();
        // stage A (128 rows): one row per thread
        {
            const int r = tid;
            const long ra = (long)(m0 + r) * lda;
            if (fast) {
                const uint4* s0 = (const uint4*)(A + ra + kb);
                const uint4* s1 = (const uint4*)(A + ra + C + kb);
                uint4* d0 = (uint4*)(sAhi + r * PITCH);
                uint4* d1 = (uint4*)(sAlo + r * PITCH);
#pragma unroll
                for (int q = 0; q < 4; q++) { d0[q] = s0[q]; d1[q] = s1[q]; }
            } else {
                for (int j = 0; j < 32; j++) {
                    bool ok = (j < vc);
                    sAhi[r * PITCH + j] = ok ? A[ra + kb + j] : zb;
                    sAlo[r * PITCH + j] = ok ? A[ra + C + kb + j] : zb;
                }
            }
        }
        // stage B (64 rows): threads 0..63
        if (tid < 64) {
            const int r = tid;
            const int o = o0 + r;
            if (o < O) {
                const long rb = (long)o * ldb;
                if (fast) {
                    const uint4* s0 = (const uint4*)(B + rb + kb);
                    const uint4* s1 = (const uint4*)(B + rb + C + kb);
                    uint4* d0 = (uint4*)(sBhi + r * PITCH);
                    uint4* d1 = (uint4*)(sBlo + r * PITCH);
#pragma unroll
                    for (int q = 0; q < 4; q++) { d0[q] = s0[q]; d1[q] = s1[q]; }
                } else {
                    for (int j = 0; j < 32; j++) {
                        bool ok = (j < vc);
                        sBhi[r * PITCH + j] = ok ? B[rb + kb + j] : zb;
                        sBlo[r * PITCH + j] = ok ? B[rb + C + kb + j] : zb;
                    }
                }
            } else {
                uint4 z4 = {0, 0, 0, 0};
                uint4* d0 = (uint4*)(sBhi + r * PITCH);
                uint4* d1 = (uint4*)(sBlo + r * PITCH);
#pragma unroll
                for (int q = 0; q < 4; q++) { d0[q] = z4; d1[q] = z4; }
            }
        }
        __syncthreads();

#pragma unroll
        for (int ks = 0; ks < 2; ks++) {
            const int k0 = ks * 16;
            uint32_t ah[2][4], al[2][4], bh[4][4], bl[4][4];
            const int arow = lane & 15;
            const int acol = k0 + ((lane >> 4) << 3);
#pragma unroll
            for (int i = 0; i < 2; i++) {
                uint32_t off = ((w * 32 + i * 16 + arow) * PITCH + acol) * 2;
                ldsm_x4(ah[i], uAhi + off);
                ldsm_x4(al[i], uAlo + off);
            }
            const int seg = lane >> 3;
            const int brow = (lane & 7) + ((seg & 2) << 2);
            const int bcol = k0 + ((seg & 1) << 3);
#pragma unroll
            for (int jp = 0; jp < 4; jp++) {
                uint32_t off = ((jp * 16 + brow) * PITCH + bcol) * 2;
                ldsm_x4(bh[jp], uBhi + off);
                ldsm_x4(bl[jp], uBlo + off);
            }
#pragma unroll
            for (int i = 0; i < 2; i++)
#pragma unroll
                for (int jp = 0; jp < 4; jp++) {
                    mma16816(acc[i][2 * jp],     ah[i], bh[jp][0], bh[jp][1]);
                    mma16816(acc[i][2 * jp + 1], ah[i], bh[jp][2], bh[jp][3]);
                    mma16816(acc[i][2 * jp],     ah[i], bl[jp][0], bl[jp][1]);
                    mma16816(acc[i][2 * jp + 1], ah[i], bl[jp][2], bl[jp][3]);
                    mma16816(acc[i][2 * jp],     al[i], bh[jp][0], bh[jp][1]);
                    mma16816(acc[i][2 * jp + 1], al[i], bh[jp][2], bh[jp][3]);
                }
        }
    }

    // epilogue: fragment layout -> global, fused activation (+optional split)
    const int qrow = lane >> 2, qcol = (lane & 3) * 2;
    const int half = ldso >> 1;
#pragma unroll
    for (int i = 0; i < 2; i++) {
        const int mA = m0 + w * 32 + i * 16 + qrow;
#pragma unroll
        for (int j = 0; j < 8; j++) {
            const int o = o0 + j * 8 + qcol;
#pragma unroll
            for (int q = 0; q < 4; q++) {
                const int m = mA + ((q >> 1) ? 8 : 0);
                const int oo = o + (q & 1);
                if (oo >= O) continue;
                float v = acc[i][j][q];
                if (MODE == 1) { v = s[oo] * v + t[oo]; v = v >= 0.f ? v : 0.2f * v; }
                else if (MODE == 2) {
                    v = s[oo] * (v + gadd[(m >> 11) * O + oo]) + t[oo];
                    v = v >= 0.f ? v : 0.2f * v;
                }
                else if (MODE == 3) { v = v + t[oo]; }
                Out[(long)m * ldo + oo] = v;
                if (So) {
                    __nv_bfloat16 h = __float2bfloat16(v);
                    So[(long)m * ldso + oo] = h;
                    So[(long)m * ldso + half + oo] =
                        __float2bfloat16(v - __bfloat162float(h));
                }
            }
        }
    }
}

// ---------------- deterministic column means ---------------------------------
// partial sums: grid (C/32, 64), block 256; slice = 256 rows
__global__ void __launch_bounds__(256) colsum_part(
    const float* __restrict__ X, int ldx, float* __restrict__ msum, int C)
{
    __shared__ float sh[8][33];
    const int lane = threadIdx.x & 31, w = threadIdx.x >> 5;
    const int c = blockIdx.x * 32 + lane;
    const int base = blockIdx.y * 256;
    float a = 0.f;
    for (int r = w; r < 256; r += 8) a += X[(long)(base + r) * ldx + c];
    sh[w][lane] = a;
    __syncthreads();
    if (w == 0) {
        float sfull = 0.f;
#pragma unroll
        for (int i = 0; i < 8; i++) sfull += sh[i][lane];
        msum[blockIdx.y * C + c] = sfull;
    }
}
__global__ void colmean_fin(const float* __restrict__ msum,
                            float* __restrict__ mean, int C)
{
    int c = threadIdx.x;
    if (c >= C) return;
    float sfull = 0.f;
    for (int i = 0; i < 64; i++) sfull += msum[i * C + c];
    mean[c] = sfull * (1.f / MTOT);
}

// ---------------- fp32 -> split bf16 [hi|lo] ---------------------------------
__global__ void conv_split(const float* __restrict__ X, int ldx, int C, int Mrows,
                           __nv_bfloat16* __restrict__ Y)
{
    long i = (long)blockIdx.x * blockDim.x + threadIdx.x;
    long tot = (long)Mrows * C;
    if (i >= tot) return;
    int m = (int)(i / C), c = (int)(i - (long)m * C);
    float x = X[(long)m * ldx + c];
    __nv_bfloat16 h = __float2bfloat16(x);
    Y[(long)m * 2 * C + c] = h;
    Y[(long)m * 2 * C + C + c] = __float2bfloat16(x - __bfloat162float(h));
}

// ---------------- fp32 -> centered split bf16 (kNN Gram) ---------------------
__global__ void conv_split_center(const float* __restrict__ X, int ldx, int C,
                                  const float* __restrict__ mean,
                                  __nv_bfloat16* __restrict__ Y)
{
    long i = (long)blockIdx.x * blockDim.x + threadIdx.x;
    long tot = (long)MTOT * C;
    if (i >= tot) return;
    int m = (int)(i / C), c = (int)(i - (long)m * C);
    float x = X[(long)m * ldx + c] - mean[c];
    __nv_bfloat16 h = __float2bfloat16(x);
    Y[(long)m * 2 * C + c] = h;
    Y[(long)m * 2 * C + C + c] = __float2bfloat16(x - __bfloat162float(h));
}

// ---------------- [W1 ; W2-W1] directly to split bf16 ------------------------
__global__ void prep_wc_split(const float* __restrict__ w,
                              __nv_bfloat16* __restrict__ wcb, int O, int C)
{
    int i = blockIdx.x * blockDim.x + threadIdx.x;
    if (i >= O * C) return;
    int o = i / C, c = i - o * C;
    float w1 = w[(long)o * 2 * C + c];
    float w2 = w[(long)o * 2 * C + C + c];
    __nv_bfloat16 h1b = __float2bfloat16(w1);
    wcb[(long)o * 2 * C + c] = h1b;
    wcb[(long)o * 2 * C + C + c] = __float2bfloat16(w1 - __bfloat162float(h1b));
    float d = w2 - w1;
    __nv_bfloat16 h2b = __float2bfloat16(d);
    wcb[(long)(O + o) * 2 * C + c] = h2b;
    wcb[(long)(O + o) * 2 * C + C + c] = __float2bfloat16(d - __bfloat162float(h2b));
}

// ---------------- centered squared row norms ---------------------------------
__global__ void rownorm_center(const float* __restrict__ X, int ldx, int C,
                               const float* __restrict__ mean,
                               float* __restrict__ xx)
{
    int m = blockIdx.x * blockDim.x + threadIdx.x;
    if (m >= MTOT) return;
    const float* p = X + (long)m * ldx;
    float a = 0.f;
    for (int c = 0; c < C; c++) { float d = p[c] - mean[c]; a += d * d; }
    xx[m] = a;
}

// ======== 1-barrier top-20 extraction core (parity-buffered wv/wi) ==========
// Each thread holds 16 distances in v[]; cached local min (mv, ms).
// Per iteration: warp lex-reduce -> wv/wi[parity] -> ONE barrier -> all
// threads redundantly compute block-min -> winner rescans its registers.
#define TOPK_EXTRACT(v, mv, ms, row, idxout)                                   \
    for (int itk = 0; itk < 20; itk++) {                                       \
        const int pb = itk & 1;                                                \
        float bv = mv;                                                         \
        int bidx = ms * 128 + tid;                                             \
        _Pragma("unroll")                                                      \
        for (int off = 16; off > 0; off >>= 1) {                               \
            float ov = __shfl_down_sync(0xFFFFFFFFu, bv, off);                 \
            int oi = __shfl_down_sync(0xFFFFFFFFu, bidx, off);                 \
            if (ov < bv || (ov == bv && oi < bidx)) { bv = ov; bidx = oi; }    \
        }                                                                      \
        if (lane == 0) { wv[pb][wrp] = bv; wi[pb][wrp] = bidx; }               \
        __syncthreads();                                                       \
        float fv = wv[pb][0];                                                  \
        int fi = wi[pb][0];                                                    \
        _Pragma("unroll")                                                      \
        for (int ww = 1; ww < 4; ww++)                                         \
            if (wv[pb][ww] < fv || (wv[pb][ww] == fv && wi[pb][ww] < fi)) {    \
                fv = wv[pb][ww]; fi = wi[pb][ww];                              \
            }                                                                  \
        if (tid == 0) idxout[(long)row * 20 + itk] = fi;                       \
        if ((fi & 127) == tid) {                                               \
            v[fi >> 7] = FLT_MAX;                                              \
            mv = v[0]; ms = 0;                                                 \
            _Pragma("unroll")                                                  \
            for (int i2 = 1; i2 < 16; i2++)                                    \
                if (v[i2] < mv) { mv = v[i2]; ms = i2; }                       \
        }                                                                      \
    }

// ---------------- layer-1 fused exact kNN (xyz from L2, slim smem) -----------
__global__ void __launch_bounds__(128) topk_xyz(
    const float* __restrict__ xyz, int* __restrict__ idxout)
{
    __shared__ float wv[2][4];
    __shared__ int   wi[2][4];

    const int row = blockIdx.x;
    const int b = row >> 11, n = row & 2047;
    const float* xb = xyz + (long)b * NPTS * 3;
    const int tid = threadIdx.x;
    const int lane = tid & 31, wrp = tid >> 5;

    const float xi = xb[n * 3], yi = xb[n * 3 + 1], zi = xb[n * 3 + 2];

    float v[16];
#pragma unroll
    for (int i = 0; i < 16; i++) {
        int j = i * 128 + tid;
        float dx = xb[j * 3] - xi, dy = xb[j * 3 + 1] - yi, dz = xb[j * 3 + 2] - zi;
        v[i] = dx * dx + dy * dy + dz * dz;
    }
    float mv = v[0];
    int ms = 0;
#pragma unroll
    for (int i = 1; i < 16; i++)
        if (v[i] < mv) { mv = v[i]; ms = i; }

    TOPK_EXTRACT(v, mv, ms, row, idxout)
}

// ---------------- top-20 smallest of d_j = xx_i + xx_j - 2*G[i,j] ------------
__global__ void __launch_bounds__(128) topk_kernel(
    const float* __restrict__ G, const float* __restrict__ xx,
    int* __restrict__ idxout)
{
    __shared__ float wv[2][4];
    __shared__ int   wi[2][4];

    const int row = blockIdx.x;
    const int b = row >> 11;
    const float* g = G + (long)row * NPTS;
    const float* xxb = xx + (b << 11);
    const float xi = xx[row];
    const int tid = threadIdx.x;
    const int lane = tid & 31, wrp = tid >> 5;

    float v[16];
#pragma unroll
    for (int i = 0; i < 16; i++) {
        int j = i * 128 + tid;
        v[i] = xi + xxb[j] - 2.f * g[j];
    }
    float mv = v[0];
    int ms = 0;
#pragma unroll
    for (int i = 1; i < 16; i++)
        if (v[i] < mv) { mv = v[i]; ms = i; }

    TOPK_EXTRACT(v, mv, ms, row, idxout)
}

// ---------------- gather-max over k neighbors + epilogue ---------------------
__global__ void __launch_bounds__(128) edge_max_kernel(
    const float* __restrict__ YZ, int ldyz,
    const int* __restrict__ idx,
    const float* __restrict__ s,
    const float* __restrict__ t,
    float* __restrict__ out, int ldo, int O)
{
    __shared__ int nb[20];
    int bn = blockIdx.x;
    int bbase = (bn >> 11) << 11;
    if (threadIdx.x < 20) nb[threadIdx.x] = idx[bn * 20 + threadIdx.x];
    __syncthreads();
    for (int o = threadIdx.x; o < O; o += 128) {
        float z = YZ[(long)bn * ldyz + O + o];
        float m = -FLT_MAX;
#pragma unroll
        for (int kk = 0; kk < 20; kk++) {
            float y = YZ[(long)(bbase + nb[kk]) * ldyz + o];
            m = fmaxf(m, y);
        }
        float v = s[o] * (m + z) + t[o];
        out[(long)bn * ldo + o] = v >= 0.f ? v : 0.2f * v;
    }
}

// ---------------- global max over N (coalesced) ------------------------------
__global__ void __launch_bounds__(256) maxreduce_kernel(
    const float* __restrict__ xemb, float* __restrict__ glob)
{
    __shared__ float sh[8][33];
    const int lane = threadIdx.x & 31, grp = threadIdx.x >> 5;
    const int o = blockIdx.x * 32 + lane;
    const int b = blockIdx.y;
    const float* p = xemb + (long)b * NPTS * 1024 + o;
    float m = -FLT_MAX;
    for (int n = grp; n < NPTS; n += 8) m = fmaxf(m, p[(long)n * 1024]);
    sh[grp][lane] = m;
    __syncthreads();
    if (grp == 0) {
#pragma unroll
        for (int r = 1; r < 8; r++) m = fmaxf(m, sh[r][lane]);
        glob[b * 1024 + o] = m;
    }
}

// ---------------- per-batch global-feature bias for h1 -----------------------
__global__ void gbias_kernel(const float* __restrict__ h1w,
                             const float* __restrict__ glob,
                             float* __restrict__ gb)
{
    __shared__ float gsh[1024];
    int b = blockIdx.x, o = threadIdx.x;
    for (int c = threadIdx.x; c < 1024; c += 256) gsh[c] = glob[b * 1024 + c];
    __syncthreads();
    const float* wr = h1w + (long)o * 1536 + 512;
    float acc = 0.f;
    for (int c = 0; c < 1024; c++) acc += gsh[c] * wr[c];
    gb[b * 256 + o] = acc;
}

// ---------------- host orchestration -----------------------------------------
static inline dim3 tgrid(int M, int O, int Z) {
    return dim3((O + 63) / 64, (M + 127) / 128, Z);
}
static inline int cgrid(long n) { return (int)((n + 255) / 256); }

// layers 2-4: centered split-bf16 Gram kNN + split-bf16 YZ GEMM
static void run_edge_layer_tc(const float* X, int ldx, int C, int O,
                              const float* w, const float* s, const float* t,
                              float* pG, float* pxx, int* pidx,
                              float* pmean, float* pmsum,
                              __nv_bfloat16* pXb, __nv_bfloat16* pXc,
                              __nv_bfloat16* pWb, float* pYZ, float* outcol)
{
    colsum_part<<<dim3(C / 32, 64), 256>>>(X, ldx, pmsum, C);
    colmean_fin<<<1, 128>>>(pmsum, pmean, C);
    conv_split_center<<<cgrid((long)MTOT * C), 256>>>(X, ldx, C, pmean, pXc);
    rownorm_center<<<cgrid(MTOT), 256>>>(X, ldx, C, pmean, pxx);
    conv_split<<<cgrid((long)MTOT * C), 256>>>(X, ldx, C, MTOT, pXb);
    prep_wc_split<<<cgrid(O * C), 256>>>(w, pWb, O, C);
    gemm_mma<0><<<tgrid(NPTS, NPTS, BATCH), 128>>>(
        pXc, 2 * C, (long)NPTS * 2 * C, pXc, 2 * C, (long)NPTS * 2 * C,
        pG, NPTS, (long)NPTS * NPTS, NPTS, C, NPTS,
        nullptr, nullptr, nullptr, nullptr, 0);
    topk_kernel<<<MTOT, 128>>>(pG, pxx, pidx);
    gemm_mma<0><<<tgrid(MTOT, 2 * O, 1), 128>>>(
        pXb, 2 * C, 0L, pWb, 2 * C, 0L, pYZ, 2 * O, 0L,
        MTOT, C, 2 * O, nullptr, nullptr, nullptr, nullptr, 0);
    edge_max_kernel<<<MTOT, 128>>>(pYZ, 2 * O, pidx, s, t, outcol, 512, O);
}

extern "C" void kernel_launch(void* const* d_in, const int* in_sizes, int n_in,
                              void* d_out, int out_size)
{
    const float* xyz    = (const float*)d_in[0];
    const float* ec1_w  = (const float*)d_in[1];
    const float* ec1_s  = (const float*)d_in[2];
    const float* ec1_t  = (const float*)d_in[3];
    const float* ec2_w  = (const float*)d_in[4];
    const float* ec2_s  = (const float*)d_in[5];
    const float* ec2_t  = (const float*)d_in[6];
    const float* ec3_w  = (const float*)d_in[7];
    const float* ec3_s  = (const float*)d_in[8];
    const float* ec3_t  = (const float*)d_in[9];
    const float* ec4_w  = (const float*)d_in[10];
    const float* ec4_s  = (const float*)d_in[11];
    const float* ec4_t  = (const float*)d_in[12];
    const float* fuse_w = (const float*)d_in[13];
    const float* fuse_s = (const float*)d_in[14];
    const float* fuse_t = (const float*)d_in[15];
    const float* emb_w  = (const float*)d_in[16];
    const float* emb_s  = (const float*)d_in[17];
    const float* emb_t  = (const float*)d_in[18];
    const float* h1_w   = (const float*)d_in[19];
    const float* h1_s   = (const float*)d_in[20];
    const float* h1_t   = (const float*)d_in[21];
    const float* h2_w   = (const float*)d_in[22];
    const float* h2_s   = (const float*)d_in[23];
    const float* h2_t   = (const float*)d_in[24];
    const float* h3_w   = (const float*)d_in[25];
    const float* h3_b   = (const float*)d_in[26];
    float* out = (float*)d_out;

    float *pG, *pxcat, *pYZ, *pxloc, *pxemb, *ph1, *ph2, *pxx, *pglob, *pgb;
    float *pmean, *pmsum;
    __nv_bfloat16 *pXb, *pXb2, *pXc, *pWb;
    int* pidx;
    cudaGetSymbolAddress((void**)&pG, g_G);
    cudaGetSymbolAddress((void**)&pxcat, g_xcat);
    cudaGetSymbolAddress((void**)&pYZ, g_YZ);
    cudaGetSymbolAddress((void**)&pxloc, g_xlocal);
    cudaGetSymbolAddress((void**)&pxemb, g_xemb);
    cudaGetSymbolAddress((void**)&ph1, g_h1);
    cudaGetSymbolAddress((void**)&ph2, g_h2);
    cudaGetSymbolAddress((void**)&pxx, g_xx);
    cudaGetSymbolAddress((void**)&pglob, g_glob);
    cudaGetSymbolAddress((void**)&pgb, g_gbias);
    cudaGetSymbolAddress((void**)&pmean, g_mean);
    cudaGetSymbolAddress((void**)&pmsum, g_msum);
    cudaGetSymbolAddress((void**)&pXb, g_Xb);
    cudaGetSymbolAddress((void**)&pXb2, g_Xb2);
    cudaGetSymbolAddress((void**)&pXc, g_Xc);
    cudaGetSymbolAddress((void**)&pWb, g_Wb);
    cudaGetSymbolAddress((void**)&pidx, g_idx);

    // ---- layer 1: exact fused kNN on xyz (slim), split-bf16 YZ (C=3) --------
    conv_split<<<cgrid((long)MTOT * 3), 256>>>(xyz, 3, 3, MTOT, pXb);
    prep_wc_split<<<cgrid(64 * 3), 256>>>(ec1_w, pWb, 64, 3);
    gemm_mma<0><<<tgrid(MTOT, 128, 1), 128>>>(
        pXb, 6, 0L, pWb, 6, 0L, pYZ, 128, 0L,
        MTOT, 3, 128, nullptr, nullptr, nullptr, nullptr, 0);
    topk_xyz<<<MTOT, 128>>>(xyz, pidx);
    edge_max_kernel<<<MTOT, 128>>>(pYZ, 128, pidx, ec1_s, ec1_t, pxcat + 0, 512, 64);

    // ---- layers 2-4 ----
    run_edge_layer_tc(pxcat + 0,   512, 64,  64,  ec2_w, ec2_s, ec2_t,
                      pG, pxx, pidx, pmean, pmsum, pXb, pXc, pWb, pYZ, pxcat + 64);
    run_edge_layer_tc(pxcat + 64,  512, 64,  128, ec3_w, ec3_s, ec3_t,
                      pG, pxx, pidx, pmean, pmsum, pXb, pXc, pWb, pYZ, pxcat + 128);
    run_edge_layer_tc(pxcat + 128, 512, 128, 256, ec4_w, ec4_s, ec4_t,
                      pG, pxx, pidx, pmean, pmsum, pXb, pXc, pWb, pYZ, pxcat + 256);

    // fuse: (16384,512) -> 512, lrelu; split output fused into epilogue
    conv_split<<<cgrid((long)MTOT * 512), 256>>>(pxcat, 512, 512, MTOT, pXb);
    conv_split<<<cgrid(512L * 512), 256>>>(fuse_w, 512, 512, 512, pWb);
    gemm_mma<1><<<tgrid(MTOT, 512, 1), 128>>>(
        pXb, 1024, 0L, pWb, 1024, 0L, pxloc, 512, 0L,
        MTOT, 512, 512, fuse_s, fuse_t, nullptr, pXb2, 1024);
    // emb: 512 -> 1024, lrelu (consumes fused split)
    conv_split<<<cgrid(1024L * 512), 256>>>(emb_w, 512, 512, 1024, pWb);
    gemm_mma<1><<<tgrid(MTOT, 1024, 1), 128>>>(
        pXb2, 1024, 0L, pWb, 1024, 0L, pxemb, 1024, 0L,
        MTOT, 512, 1024, emb_s, emb_t, nullptr, nullptr, 0);
    // global max over N + per-batch bias via h1_w[:,512:]
    maxreduce_kernel<<<dim3(32, BATCH), 256>>>(pxemb, pglob);
    gbias_kernel<<<BATCH, 256>>>(h1_w, pglob, pgb);
    // h1: 512 -> 256 with per-batch gadd, lrelu; split out -> pXb
    conv_split<<<cgrid(256L * 512), 256>>>(h1_w, 1536, 512, 256, pWb);
    gemm_mma<2><<<tgrid(MTOT, 256, 1), 128>>>(
        pXb2, 1024, 0L, pWb, 1024, 0L, ph1, 256, 0L,
        MTOT, 512, 256, h1_s, h1_t, pgb, pXb, 512);
    // h2: 256 -> 256, lrelu; split out -> pXb2
    conv_split<<<cgrid(256L * 256), 256>>>(h2_w, 256, 256, 256, pWb);
    gemm_mma<1><<<tgrid(MTOT, 256, 1), 128>>>(
        pXb, 512, 0L, pWb, 512, 0L, ph2, 256, 0L,
        MTOT, 256, 256, h2_s, h2_t, nullptr, pXb2, 512);
    // h3: 256 -> 13, +bias -> d_out
    conv_split<<<cgrid(13L * 256), 256>>>(h3_w, 256, 256, 13, pWb);
    gemm_mma<3><<<tgrid(MTOT, 13, 1), 128>>>(
        pXb2, 512, 0L, pWb, 512, 0L, out, 13, 0L,
        MTOT, 256, 13, nullptr, h3_b, nullptr, nullptr, 0);
}

// round 12
// speedup vs baseline: 1.4634x; 1.0640x over previous
#include <cuda_runtime.h>
#include <cuda_bf16.h>
#include <float.h>
#include <stdint.h>

#define NPTS 2048
#define BATCH 8
#define MTOT (BATCH * NPTS)

// ---------------- scratch (device globals; no runtime allocation) ------------
__device__ float g_G[(size_t)BATCH * NPTS * NPTS];   // 128 MB dist/Gram scratch
__device__ float g_xcat[(size_t)MTOT * 512];
__device__ float g_YZ[(size_t)MTOT * 512];
__device__ float g_xlocal[(size_t)MTOT * 512];
__device__ float g_xemb[(size_t)MTOT * 1024];
__device__ float g_h1[(size_t)MTOT * 256];
__device__ float g_h2[(size_t)MTOT * 256];
__device__ float g_xx[MTOT];
__device__ int   g_idx[MTOT * 20];
__device__ float g_glob[BATCH * 1024];
__device__ float g_gbias[BATCH * 256];
__device__ float g_mean[512];
__device__ float g_msum[64 * 512];
__device__ __nv_bfloat16 g_Xb[(size_t)MTOT * 1024];  // xcat split [hi512|lo512]
__device__ __nv_bfloat16 g_Xb2[(size_t)MTOT * 1024]; // split scratch B
__device__ __nv_bfloat16 g_Xc[(size_t)MTOT * 256];   // centered split / xyz split
__device__ __nv_bfloat16 g_Wb[(size_t)1024 * 1024];  // split weights

// ---------------- warp-mma helpers -------------------------------------------
__device__ __forceinline__ uint32_t smem_u32(const void* p) {
    uint32_t a;
    asm("{ .reg .u64 t; cvta.to.shared.u64 t, %1; cvt.u32.u64 %0, t; }"
        : "=r"(a) : "l"(p));
    return a;
}
__device__ __forceinline__ void ldsm_x4(uint32_t* r, uint32_t addr) {
    asm volatile("ldmatrix.sync.aligned.m8n8.x4.shared.b16 {%0,%1,%2,%3}, [%4];"
                 : "=r"(r[0]), "=r"(r[1]), "=r"(r[2]), "=r"(r[3]) : "r"(addr));
}
__device__ __forceinline__ void mma16816(float* c, const uint32_t* a,
                                         uint32_t b0, uint32_t b1) {
    asm volatile(
        "mma.sync.aligned.m16n8k16.row.col.f32.bf16.bf16.f32 "
        "{%0,%1,%2,%3}, {%4,%5,%6,%7}, {%8,%9}, {%0,%1,%2,%3};"
        : "+f"(c[0]), "+f"(c[1]), "+f"(c[2]), "+f"(c[3])
        : "r"(a[0]), "r"(a[1]), "r"(a[2]), "r"(a[3]), "r"(b0), "r"(b1));
}

#define PITCH 40   // smem row pitch in bf16 (80B: conflict-free ldmatrix)

// ---------------- split-bf16 tensor GEMM: out[m,o] = sum_c X[m,c]*W[o,c] -----
// A rows: hi at [c], lo at [loA + c]. B rows: hi at [c], lo at [loB + c].
// Accumulate hi*hi + hi*lo + lo*hi in fp32 via mma.sync.
// 256 threads: 8 warps of 32(M)x32(O) micro-tiles over a 128x64 CTA tile.
// Optional So/ldso: also emit split-bf16 [hi|lo] (lo at +ldso/2) of output.
// MODE 0: raw  1: lrelu(s*v+t)  2: lrelu(s*(v+gadd[b,o])+t)  3: v+t[o]
template <int MODE>
__global__ void __launch_bounds__(256) gemm_mma(
    const __nv_bfloat16* __restrict__ Ab, int lda, long bsA, int loA,
    const __nv_bfloat16* __restrict__ Bb, int ldb, long bsB, int loB,
    float* __restrict__ Ob, int ldo, long bsO,
    int M, int C, int O,
    const float* __restrict__ s, const float* __restrict__ t,
    const float* __restrict__ gadd,
    __nv_bfloat16* __restrict__ So, int ldso)
{
    __shared__ __align__(16) __nv_bfloat16 sAhi[128 * PITCH];
    __shared__ __align__(16) __nv_bfloat16 sAlo[128 * PITCH];
    __shared__ __align__(16) __nv_bfloat16 sBhi[64 * PITCH];
    __shared__ __align__(16) __nv_bfloat16 sBlo[64 * PITCH];

    const __nv_bfloat16* A = Ab + (long)blockIdx.z * bsA;
    const __nv_bfloat16* B = Bb + (long)blockIdx.z * bsB;
    float* Out = Ob + (long)blockIdx.z * bsO;
    const int m0 = blockIdx.y * 128, o0 = blockIdx.x * 64;
    const int tid = threadIdx.x, lane = tid & 31, wid = tid >> 5;
    const int wm = wid & 3, wo = wid >> 2;      // warp tile: rows wm*32, cols wo*32
    const __nv_bfloat16 zb = __float2bfloat16(0.0f);

    const uint32_t uAhi = smem_u32(sAhi), uAlo = smem_u32(sAlo);
    const uint32_t uBhi = smem_u32(sBhi), uBlo = smem_u32(sBlo);

    float acc[2][4][4];
#pragma unroll
    for (int i = 0; i < 2; i++)
#pragma unroll
        for (int j = 0; j < 4; j++)
#pragma unroll
            for (int q = 0; q < 4; q++) acc[i][j][q] = 0.f;

    const int nch = (C + 31) >> 5;
    const bool fastv = ((lda & 7) == 0) && ((ldb & 7) == 0) && ((C & 7) == 0);

    for (int cc = 0; cc < nch; cc++) {
        const int kb = cc * 32;
        int vc = C - kb; if (vc > 32) vc = 32;
        const bool fast = fastv && (vc == 32);

        __syncthreads();
        if (tid < 128) {
            // stage A row r = tid
            const int r = tid;
            const long ra = (long)(m0 + r) * lda;
            if (fast) {
                const uint4* s0 = (const uint4*)(A + ra + kb);
                const uint4* s1 = (const uint4*)(A + ra + loA + kb);
                uint4* d0 = (uint4*)(sAhi + r * PITCH);
                uint4* d1 = (uint4*)(sAlo + r * PITCH);
#pragma unroll
                for (int q = 0; q < 4; q++) { d0[q] = s0[q]; d1[q] = s1[q]; }
            } else {
                for (int j = 0; j < 32; j++) {
                    bool ok = (j < vc);
                    sAhi[r * PITCH + j] = ok ? A[ra + kb + j] : zb;
                    sAlo[r * PITCH + j] = ok ? A[ra + loA + kb + j] : zb;
                }
            }
        } else if (tid < 192) {
            // stage B row r = tid-128
            const int r = tid - 128;
            const int o = o0 + r;
            if (o < O) {
                const long rb = (long)o * ldb;
                if (fast) {
                    const uint4* s0 = (const uint4*)(B + rb + kb);
                    const uint4* s1 = (const uint4*)(B + rb + loB + kb);
                    uint4* d0 = (uint4*)(sBhi + r * PITCH);
                    uint4* d1 = (uint4*)(sBlo + r * PITCH);
#pragma unroll
                    for (int q = 0; q < 4; q++) { d0[q] = s0[q]; d1[q] = s1[q]; }
                } else {
                    for (int j = 0; j < 32; j++) {
                        bool ok = (j < vc);
                        sBhi[r * PITCH + j] = ok ? B[rb + kb + j] : zb;
                        sBlo[r * PITCH + j] = ok ? B[rb + loB + kb + j] : zb;
                    }
                }
            } else {
                uint4 z4 = {0, 0, 0, 0};
                uint4* d0 = (uint4*)(sBhi + r * PITCH);
                uint4* d1 = (uint4*)(sBlo + r * PITCH);
#pragma unroll
                for (int q = 0; q < 4; q++) { d0[q] = z4; d1[q] = z4; }
            }
        }
        __syncthreads();

#pragma unroll
        for (int ks = 0; ks < 2; ks++) {
            const int k0 = ks * 16;
            uint32_t ah[2][4], al[2][4], bh[2][4], bl[2][4];
            const int arow = lane & 15;
            const int acol = k0 + ((lane >> 4) << 3);
#pragma unroll
            for (int i = 0; i < 2; i++) {
                uint32_t off = ((wm * 32 + i * 16 + arow) * PITCH + acol) * 2;
                ldsm_x4(ah[i], uAhi + off);
                ldsm_x4(al[i], uAlo + off);
            }
            const int seg = lane >> 3;
            const int brow = (lane & 7) + ((seg & 2) << 2);
            const int bcol = k0 + ((seg & 1) << 3);
#pragma unroll
            for (int jp = 0; jp < 2; jp++) {
                uint32_t off = ((wo * 32 + jp * 16 + brow) * PITCH + bcol) * 2;
                ldsm_x4(bh[jp], uBhi + off);
                ldsm_x4(bl[jp], uBlo + off);
            }
#pragma unroll
            for (int i = 0; i < 2; i++)
#pragma unroll
                for (int jp = 0; jp < 2; jp++) {
                    mma16816(acc[i][2 * jp],     ah[i], bh[jp][0], bh[jp][1]);
                    mma16816(acc[i][2 * jp + 1], ah[i], bh[jp][2], bh[jp][3]);
                    mma16816(acc[i][2 * jp],     ah[i], bl[jp][0], bl[jp][1]);
                    mma16816(acc[i][2 * jp + 1], ah[i], bl[jp][2], bl[jp][3]);
                    mma16816(acc[i][2 * jp],     al[i], bh[jp][0], bh[jp][1]);
                    mma16816(acc[i][2 * jp + 1], al[i], bh[jp][2], bh[jp][3]);
                }
        }
    }

    // epilogue: fragment layout -> global, fused activation (+optional split)
    const int qrow = lane >> 2, qcol = (lane & 3) * 2;
    const int half = ldso >> 1;
#pragma unroll
    for (int i = 0; i < 2; i++) {
        const int mA = m0 + wm * 32 + i * 16 + qrow;
#pragma unroll
        for (int j = 0; j < 4; j++) {
            const int o = o0 + wo * 32 + j * 8 + qcol;
#pragma unroll
            for (int q = 0; q < 4; q++) {
                const int m = mA + ((q >> 1) ? 8 : 0);
                const int oo = o + (q & 1);
                if (oo >= O) continue;
                float v = acc[i][j][q];
                if (MODE == 1) { v = s[oo] * v + t[oo]; v = v >= 0.f ? v : 0.2f * v; }
                else if (MODE == 2) {
                    v = s[oo] * (v + gadd[(m >> 11) * O + oo]) + t[oo];
                    v = v >= 0.f ? v : 0.2f * v;
                }
                else if (MODE == 3) { v = v + t[oo]; }
                Out[(long)m * ldo + oo] = v;
                if (So) {
                    __nv_bfloat16 h = __float2bfloat16(v);
                    So[(long)m * ldso + oo] = h;
                    So[(long)m * ldso + half + oo] =
                        __float2bfloat16(v - __bfloat162float(h));
                }
            }
        }
    }
}

// ---------------- deterministic column means ---------------------------------
__global__ void __launch_bounds__(256) colsum_part(
    const float* __restrict__ X, int ldx, float* __restrict__ msum, int C)
{
    __shared__ float sh[8][33];
    const int lane = threadIdx.x & 31, w = threadIdx.x >> 5;
    const int c = blockIdx.x * 32 + lane;
    const int base = blockIdx.y * 256;
    float a = 0.f;
    for (int r = w; r < 256; r += 8) a += X[(long)(base + r) * ldx + c];
    sh[w][lane] = a;
    __syncthreads();
    if (w == 0) {
        float sfull = 0.f;
#pragma unroll
        for (int i = 0; i < 8; i++) sfull += sh[i][lane];
        msum[blockIdx.y * C + c] = sfull;
    }
}
__global__ void colmean_fin(const float* __restrict__ msum,
                            float* __restrict__ mean, int C)
{
    int c = threadIdx.x;
    if (c >= C) return;
    float sfull = 0.f;
    for (int i = 0; i < 64; i++) sfull += msum[i * C + c];
    mean[c] = sfull * (1.f / MTOT);
}

// ---------------- fused center + split + row-norm (blockDim == C) ------------
__global__ void center_split_norm(const float* __restrict__ X, int ldx, int C,
                                  const float* __restrict__ mean,
                                  __nv_bfloat16* __restrict__ Xc,
                                  float* __restrict__ xx)
{
    __shared__ float sh[4];
    const int row = blockIdx.x, tid = threadIdx.x;
    const int lane = tid & 31, wrp = tid >> 5;
    float x = X[(long)row * ldx + tid] - mean[tid];
    __nv_bfloat16 h = __float2bfloat16(x);
    Xc[(long)row * 2 * C + tid] = h;
    Xc[(long)row * 2 * C + C + tid] = __float2bfloat16(x - __bfloat162float(h));
    float a = x * x;
#pragma unroll
    for (int off = 16; off > 0; off >>= 1) a += __shfl_down_sync(0xFFFFFFFFu, a, off);
    if (lane == 0) sh[wrp] = a;
    __syncthreads();
    if (tid == 0) {
        float tot = 0.f;
        for (int i = 0; i < (C >> 5); i++) tot += sh[i];
        xx[row] = tot;
    }
}

// ---------------- fp32 -> split bf16 [hi|lo] (weights / xyz) -----------------
__global__ void conv_split(const float* __restrict__ X, int ldx, int C, int Mrows,
                           __nv_bfloat16* __restrict__ Y)
{
    long i = (long)blockIdx.x * blockDim.x + threadIdx.x;
    long tot = (long)Mrows * C;
    if (i >= tot) return;
    int m = (int)(i / C), c = (int)(i - (long)m * C);
    float x = X[(long)m * ldx + c];
    __nv_bfloat16 h = __float2bfloat16(x);
    Y[(long)m * 2 * C + c] = h;
    Y[(long)m * 2 * C + C + c] = __float2bfloat16(x - __bfloat162float(h));
}

// ---------------- [W1 ; W2-W1] directly to split bf16 ------------------------
__global__ void prep_wc_split(const float* __restrict__ w,
                              __nv_bfloat16* __restrict__ wcb, int O, int C)
{
    int i = blockIdx.x * blockDim.x + threadIdx.x;
    if (i >= O * C) return;
    int o = i / C, c = i - o * C;
    float w1 = w[(long)o * 2 * C + c];
    float w2 = w[(long)o * 2 * C + C + c];
    __nv_bfloat16 h1b = __float2bfloat16(w1);
    wcb[(long)o * 2 * C + c] = h1b;
    wcb[(long)o * 2 * C + C + c] = __float2bfloat16(w1 - __bfloat162float(h1b));
    float d = w2 - w1;
    __nv_bfloat16 h2b = __float2bfloat16(d);
    wcb[(long)(O + o) * 2 * C + c] = h2b;
    wcb[(long)(O + o) * 2 * C + C + c] = __float2bfloat16(d - __bfloat162float(h2b));
}

// ======== 1-barrier top-20 extraction core (parity-buffered wv/wi) ==========
#define TOPK_EXTRACT(v, mv, ms, row, idxout)                                   \
    for (int itk = 0; itk < 20; itk++) {                                       \
        const int pb = itk & 1;                                                \
        float bv = mv;                                                         \
        int bidx = ms * 128 + tid;                                             \
        _Pragma("unroll")                                                      \
        for (int off = 16; off > 0; off >>= 1) {                               \
            float ov = __shfl_down_sync(0xFFFFFFFFu, bv, off);                 \
            int oi = __shfl_down_sync(0xFFFFFFFFu, bidx, off);                 \
            if (ov < bv || (ov == bv && oi < bidx)) { bv = ov; bidx = oi; }    \
        }                                                                      \
        if (lane == 0) { wv[pb][wrp] = bv; wi[pb][wrp] = bidx; }               \
        __syncthreads();                                                       \
        float fv = wv[pb][0];                                                  \
        int fi = wi[pb][0];                                                    \
        _Pragma("unroll")                                                      \
        for (int ww = 1; ww < 4; ww++)                                         \
            if (wv[pb][ww] < fv || (wv[pb][ww] == fv && wi[pb][ww] < fi)) {    \
                fv = wv[pb][ww]; fi = wi[pb][ww];                              \
            }                                                                  \
        if (tid == 0) idxout[(long)row * 20 + itk] = fi;                       \
        if ((fi & 127) == tid) {                                               \
            v[fi >> 7] = FLT_MAX;                                              \
            mv = v[0]; ms = 0;                                                 \
            _Pragma("unroll")                                                  \
            for (int i2 = 1; i2 < 16; i2++)                                    \
                if (v[i2] < mv) { mv = v[i2]; ms = i2; }                       \
        }                                                                      \
    }

// ---------------- layer-1 fused exact kNN (xyz from L2, slim smem) -----------
__global__ void __launch_bounds__(128) topk_xyz(
    const float* __restrict__ xyz, int* __restrict__ idxout)
{
    __shared__ float wv[2][4];
    __shared__ int   wi[2][4];

    const int row = blockIdx.x;
    const int b = row >> 11, n = row & 2047;
    const float* xb = xyz + (long)b * NPTS * 3;
    const int tid = threadIdx.x;
    const int lane = tid & 31, wrp = tid >> 5;

    const float xi = xb[n * 3], yi = xb[n * 3 + 1], zi = xb[n * 3 + 2];

    float v[16];
#pragma unroll
    for (int i = 0; i < 16; i++) {
        int j = i * 128 + tid;
        float dx = xb[j * 3] - xi, dy = xb[j * 3 + 1] - yi, dz = xb[j * 3 + 2] - zi;
        v[i] = dx * dx + dy * dy + dz * dz;
    }
    float mv = v[0];
    int ms = 0;
#pragma unroll
    for (int i = 1; i < 16; i++)
        if (v[i] < mv) { mv = v[i]; ms = i; }

    TOPK_EXTRACT(v, mv, ms, row, idxout)
}

// ---------------- top-20 smallest of d_j = xx_i + xx_j - 2*G[i,j] ------------
__global__ void __launch_bounds__(128) topk_kernel(
    const float* __restrict__ G, const float* __restrict__ xx,
    int* __restrict__ idxout)
{
    __shared__ float wv[2][4];
    __shared__ int   wi[2][4];

    const int row = blockIdx.x;
    const int b = row >> 11;
    const float* g = G + (long)row * NPTS;
    const float* xxb = xx + (b << 11);
    const float xi = xx[row];
    const int tid = threadIdx.x;
    const int lane = tid & 31, wrp = tid >> 5;

    float v[16];
#pragma unroll
    for (int i = 0; i < 16; i++) {
        int j = i * 128 + tid;
        v[i] = xi + xxb[j] - 2.f * g[j];
    }
    float mv = v[0];
    int ms = 0;
#pragma unroll
    for (int i = 1; i < 16; i++)
        if (v[i] < mv) { mv = v[i]; ms = i; }

    TOPK_EXTRACT(v, mv, ms, row, idxout)
}

// ---------------- gather-max + epilogue (+ fused split output) ---------------
// out fp32 [bn*ldo + o]; sout hi at [bn*1024 + o], lo at [bn*1024 + 512 + o]
__global__ void __launch_bounds__(128) edge_max_kernel(
    const float* __restrict__ YZ, int ldyz,
    const int* __restrict__ idx,
    const float* __restrict__ s,
    const float* __restrict__ t,
    float* __restrict__ out, int ldo,
    __nv_bfloat16* __restrict__ sout, int O)
{
    __shared__ int nb[20];
    int bn = blockIdx.x;
    int bbase = (bn >> 11) << 11;
    if (threadIdx.x < 20) nb[threadIdx.x] = idx[bn * 20 + threadIdx.x];
    __syncthreads();
    for (int o = threadIdx.x; o < O; o += 128) {
        float z = YZ[(long)bn * ldyz + O + o];
        float m = -FLT_MAX;
#pragma unroll
        for (int kk = 0; kk < 20; kk++) {
            float y = YZ[(long)(bbase + nb[kk]) * ldyz + o];
            m = fmaxf(m, y);
        }
        float v = s[o] * (m + z) + t[o];
        v = v >= 0.f ? v : 0.2f * v;
        out[(long)bn * ldo + o] = v;
        __nv_bfloat16 h = __float2bfloat16(v);
        sout[(long)bn * 1024 + o] = h;
        sout[(long)bn * 1024 + 512 + o] = __float2bfloat16(v - __bfloat162float(h));
    }
}

// ---------------- global max over N (coalesced) ------------------------------
__global__ void __launch_bounds__(256) maxreduce_kernel(
    const float* __restrict__ xemb, float* __restrict__ glob)
{
    __shared__ float sh[8][33];
    const int lane = threadIdx.x & 31, grp = threadIdx.x >> 5;
    const int o = blockIdx.x * 32 + lane;
    const int b = blockIdx.y;
    const float* p = xemb + (long)b * NPTS * 1024 + o;
    float m = -FLT_MAX;
    for (int n = grp; n < NPTS; n += 8) m = fmaxf(m, p[(long)n * 1024]);
    sh[grp][lane] = m;
    __syncthreads();
    if (grp == 0) {
#pragma unroll
        for (int r = 1; r < 8; r++) m = fmaxf(m, sh[r][lane]);
        glob[b * 1024 + o] = m;
    }
}

// ---------------- per-batch global-feature bias for h1 -----------------------
__global__ void gbias_kernel(const float* __restrict__ h1w,
                             const float* __restrict__ glob,
                             float* __restrict__ gb)
{
    __shared__ float gsh[1024];
    int b = blockIdx.x, o = threadIdx.x;
    for (int c = threadIdx.x; c < 1024; c += 256) gsh[c] = glob[b * 1024 + c];
    __syncthreads();
    const float* wr = h1w + (long)o * 1536 + 512;
    float acc = 0.f;
    for (int c = 0; c < 1024; c++) acc += gsh[c] * wr[c];
    gb[b * 256 + o] = acc;
}

// ---------------- host orchestration -----------------------------------------
static inline dim3 tgrid(int M, int O, int Z) {
    return dim3((O + 63) / 64, (M + 127) / 128, Z);
}
static inline int cgrid(long n) { return (int)((n + 255) / 256); }

// layers 2-4: centered Gram kNN + YZ GEMM reading the fused xcat split
static void run_edge_layer_tc(const float* X, int inoff, int C, int O,
                              const float* w, const float* s, const float* t,
                              float* pG, float* pxx, int* pidx,
                              float* pmean, float* pmsum,
                              __nv_bfloat16* pXb, __nv_bfloat16* pXc,
                              __nv_bfloat16* pWb, float* pYZ,
                              float* outcol, int outoff)
{
    colsum_part<<<dim3(C / 32, 64), 256>>>(X, 512, pmsum, C);
    colmean_fin<<<1, 128>>>(pmsum, pmean, C);
    center_split_norm<<<MTOT, C>>>(X, 512, C, pmean, pXc, pxx);
    prep_wc_split<<<cgrid(O * C), 256>>>(w, pWb, O, C);
    gemm_mma<0><<<tgrid(NPTS, NPTS, BATCH), 256>>>(
        pXc, 2 * C, (long)NPTS * 2 * C, C, pXc, 2 * C, (long)NPTS * 2 * C, C,
        pG, NPTS, (long)NPTS * NPTS, NPTS, C, NPTS,
        nullptr, nullptr, nullptr, nullptr, 0);
    topk_kernel<<<MTOT, 128>>>(pG, pxx, pidx);
    // YZ = X @ [W1; W2-W1]^T, A = fused xcat split at column inoff
    gemm_mma<0><<<tgrid(MTOT, 2 * O, 1), 256>>>(
        pXb + inoff, 1024, 0L, 512, pWb, 2 * C, 0L, C, pYZ, 2 * O, 0L,
        MTOT, C, 2 * O, nullptr, nullptr, nullptr, nullptr, 0);
    edge_max_kernel<<<MTOT, 128>>>(pYZ, 2 * O, pidx, s, t,
                                   outcol, 512, pXb + outoff, O);
}

extern "C" void kernel_launch(void* const* d_in, const int* in_sizes, int n_in,
                              void* d_out, int out_size)
{
    const float* xyz    = (const float*)d_in[0];
    const float* ec1_w  = (const float*)d_in[1];
    const float* ec1_s  = (const float*)d_in[2];
    const float* ec1_t  = (const float*)d_in[3];
    const float* ec2_w  = (const float*)d_in[4];
    const float* ec2_s  = (const float*)d_in[5];
    const float* ec2_t  = (const float*)d_in[6];
    const float* ec3_w  = (const float*)d_in[7];
    const float* ec3_s  = (const float*)d_in[8];
    const float* ec3_t  = (const float*)d_in[9];
    const float* ec4_w  = (const float*)d_in[10];
    const float* ec4_s  = (const float*)d_in[11];
    const float* ec4_t  = (const float*)d_in[12];
    const float* fuse_w = (const float*)d_in[13];
    const float* fuse_s = (const float*)d_in[14];
    const float* fuse_t = (const float*)d_in[15];
    const float* emb_w  = (const float*)d_in[16];
    const float* emb_s  = (const float*)d_in[17];
    const float* emb_t  = (const float*)d_in[18];
    const float* h1_w   = (const float*)d_in[19];
    const float* h1_s   = (const float*)d_in[20];
    const float* h1_t   = (const float*)d_in[21];
    const float* h2_w   = (const float*)d_in[22];
    const float* h2_s   = (const float*)d_in[23];
    const float* h2_t   = (const float*)d_in[24];
    const float* h3_w   = (const float*)d_in[25];
    const float* h3_b   = (const float*)d_in[26];
    float* out = (float*)d_out;

    float *pG, *pxcat, *pYZ, *pxloc, *pxemb, *ph1, *ph2, *pxx, *pglob, *pgb;
    float *pmean, *pmsum;
    __nv_bfloat16 *pXb, *pXb2, *pXc, *pWb;
    int* pidx;
    cudaGetSymbolAddress((void**)&pG, g_G);
    cudaGetSymbolAddress((void**)&pxcat, g_xcat);
    cudaGetSymbolAddress((void**)&pYZ, g_YZ);
    cudaGetSymbolAddress((void**)&pxloc, g_xlocal);
    cudaGetSymbolAddress((void**)&pxemb, g_xemb);
    cudaGetSymbolAddress((void**)&ph1, g_h1);
    cudaGetSymbolAddress((void**)&ph2, g_h2);
    cudaGetSymbolAddress((void**)&pxx, g_xx);
    cudaGetSymbolAddress((void**)&pglob, g_glob);
    cudaGetSymbolAddress((void**)&pgb, g_gbias);
    cudaGetSymbolAddress((void**)&pmean, g_mean);
    cudaGetSymbolAddress((void**)&pmsum, g_msum);
    cudaGetSymbolAddress((void**)&pXb, g_Xb);
    cudaGetSymbolAddress((void**)&pXb2, g_Xb2);
    cudaGetSymbolAddress((void**)&pXc, g_Xc);
    cudaGetSymbolAddress((void**)&pWb, g_Wb);
    cudaGetSymbolAddress((void**)&pidx, g_idx);

    // ---- layer 1: exact fused kNN on xyz; YZ from xyz split (C=3) -----------
    conv_split<<<cgrid((long)MTOT * 3), 256>>>(xyz, 3, 3, MTOT, pXc);
    prep_wc_split<<<cgrid(64 * 3), 256>>>(ec1_w, pWb, 64, 3);
    gemm_mma<0><<<tgrid(MTOT, 128, 1), 256>>>(
        pXc, 6, 0L, 3, pWb, 6, 0L, 3, pYZ, 128, 0L,
        MTOT, 3, 128, nullptr, nullptr, nullptr, nullptr, 0);
    topk_xyz<<<MTOT, 128>>>(xyz, pidx);
    edge_max_kernel<<<MTOT, 128>>>(pYZ, 128, pidx, ec1_s, ec1_t,
                                   pxcat + 0, 512, pXb + 0, 64);

    // ---- layers 2-4 (inputs read from xcat fp32 + fused xcat split) ---------
    run_edge_layer_tc(pxcat + 0,   0,   64,  64,  ec2_w, ec2_s, ec2_t,
                      pG, pxx, pidx, pmean, pmsum, pXb, pXc, pWb, pYZ,
                      pxcat + 64, 64);
    run_edge_layer_tc(pxcat + 64,  64,  64,  128, ec3_w, ec3_s, ec3_t,
                      pG, pxx, pidx, pmean, pmsum, pXb, pXc, pWb, pYZ,
                      pxcat + 128, 128);
    run_edge_layer_tc(pxcat + 128, 128, 128, 256, ec4_w, ec4_s, ec4_t,
                      pG, pxx, pidx, pmean, pmsum, pXb, pXc, pWb, pYZ,
                      pxcat + 256, 256);

    // fuse: (16384,512) -> 512, lrelu; split output fused into epilogue
    conv_split<<<cgrid(512L * 512), 256>>>(fuse_w, 512, 512, 512, pWb);
    gemm_mma<1><<<tgrid(MTOT, 512, 1), 256>>>(
        pXb, 1024, 0L, 512, pWb, 1024, 0L, 512, pxloc, 512, 0L,
        MTOT, 512, 512, fuse_s, fuse_t, nullptr, pXb2, 1024);
    // emb: 512 -> 1024, lrelu (consumes fused split)
    conv_split<<<cgrid(1024L * 512), 256>>>(emb_w, 512, 512, 1024, pWb);
    gemm_mma<1><<<tgrid(MTOT, 1024, 1), 256>>>(
        pXb2, 1024, 0L, 512, pWb, 1024, 0L, 512, pxemb, 1024, 0L,
        MTOT, 512, 1024, emb_s, emb_t, nullptr, nullptr, 0);
    // global max over N + per-batch bias via h1_w[:,512:]
    maxreduce_kernel<<<dim3(32, BATCH), 256>>>(pxemb, pglob);
    gbias_kernel<<<BATCH, 256>>>(h1_w, pglob, pgb);
    // h1: 512 -> 256 with per-batch gadd, lrelu; split out -> pXb
    conv_split<<<cgrid(256L * 512), 256>>>(h1_w, 1536, 512, 256, pWb);
    gemm_mma<2><<<tgrid(MTOT, 256, 1), 256>>>(
        pXb2, 1024, 0L, 512, pWb, 1024, 0L, 512, ph1, 256, 0L,
        MTOT, 512, 256, h1_s, h1_t, pgb, pXb, 512);
    // h2: 256 -> 256, lrelu; split out -> pXb2
    conv_split<<<cgrid(256L * 256), 256>>>(h2_w, 256, 256, 256, pWb);
    gemm_mma<1><<<tgrid(MTOT, 256, 1), 256>>>(
        pXb, 512, 0L, 256, pWb, 512, 0L, 256, ph2, 256, 0L,
        MTOT, 256, 256, h2_s, h2_t, nullptr, pXb2, 512);
    // h3: 256 -> 13, +bias -> d_out
    conv_split<<<cgrid(13L * 256), 256>>>(h3_w, 256, 256, 13, pWb);
    gemm_mma<3><<<tgrid(MTOT, 13, 1), 256>>>(
        pXb2, 512, 0L, 256, pWb, 512, 0L, 256, out, 13, 0L,
        MTOT, 256, 13, nullptr, h3_b, nullptr, nullptr, 0);
}

// round 14
// speedup vs baseline: 1.4972x; 1.0231x over previous
#include <cuda_runtime.h>
#include <cuda_bf16.h>
#include <float.h>
#include <stdint.h>

#define NPTS 2048
#define BATCH 8
#define MTOT (BATCH * NPTS)

// ---------------- scratch (device globals; no runtime allocation) ------------
__device__ float g_G[(size_t)BATCH * NPTS * NPTS];   // 128 MB dist scratch
__device__ float g_xcat[(size_t)MTOT * 512];
__device__ float g_YZ[(size_t)MTOT * 512];
__device__ float g_xlocal[(size_t)MTOT * 512];
__device__ float g_xemb[(size_t)MTOT * 1024];
__device__ float g_h1[(size_t)MTOT * 256];
__device__ float g_h2[(size_t)MTOT * 256];
__device__ float g_xx[MTOT];
__device__ int   g_idx[MTOT * 20];
__device__ float g_glob[BATCH * 1024];
__device__ float g_gbias[BATCH * 256];
__device__ float g_mean[512];
__device__ float g_msum[64 * 512];
__device__ __nv_bfloat16 g_Xb[(size_t)MTOT * 1024];  // xcat split [hi512|lo512]
__device__ __nv_bfloat16 g_Xb2[(size_t)MTOT * 1024]; // split scratch B
__device__ __nv_bfloat16 g_Xc[(size_t)MTOT * 256];   // centered split / xyz split
__device__ __nv_bfloat16 g_Wb[(size_t)1024 * 1024];  // split weights

// ---------------- warp-mma helpers -------------------------------------------
__device__ __forceinline__ uint32_t smem_u32(const void* p) {
    uint32_t a;
    asm("{ .reg .u64 t; cvta.to.shared.u64 t, %1; cvt.u32.u64 %0, t; }"
        : "=r"(a) : "l"(p));
    return a;
}
__device__ __forceinline__ void ldsm_x4(uint32_t* r, uint32_t addr) {
    asm volatile("ldmatrix.sync.aligned.m8n8.x4.shared.b16 {%0,%1,%2,%3}, [%4];"
                 : "=r"(r[0]), "=r"(r[1]), "=r"(r[2]), "=r"(r[3]) : "r"(addr));
}
__device__ __forceinline__ void mma16816(float* c, const uint32_t* a,
                                         uint32_t b0, uint32_t b1) {
    asm volatile(
        "mma.sync.aligned.m16n8k16.row.col.f32.bf16.bf16.f32 "
        "{%0,%1,%2,%3}, {%4,%5,%6,%7}, {%8,%9}, {%0,%1,%2,%3};"
        : "+f"(c[0]), "+f"(c[1]), "+f"(c[2]), "+f"(c[3])
        : "r"(a[0]), "r"(a[1]), "r"(a[2]), "r"(a[3]), "r"(b0), "r"(b1));
}

#define PITCH 40   // smem row pitch in bf16 (80B: conflict-free ldmatrix)

// ---------------- split-bf16 tensor GEMM: out[m,o] = sum_c X[m,c]*W[o,c] -----
// A rows: hi at [c], lo at [loA + c]. B rows: hi at [c], lo at [loB + c].
// Accumulate hi*hi + hi*lo + lo*hi in fp32 via mma.sync.
// 256 threads. CTA tile 128(M) x TILEO(O); warp tile 32 x TILEO/2.
// Optional So/ldso: also emit split-bf16 [hi|lo] (lo at +ldso/2) of output.
// MODE 0: raw  1: lrelu(s*v+t)  2: lrelu(s*(v+gadd[b,o])+t)  3: v+t[o]
// MODE 4: dist epilogue v = s[z*M+m] + t[z*M+oo] - 2v  (Gram -> distances)
template <int MODE, int TILEO>
__global__ void __launch_bounds__(256) gemm_mma(
    const __nv_bfloat16* __restrict__ Ab, int lda, long bsA, int loA,
    const __nv_bfloat16* __restrict__ Bb, int ldb, long bsB, int loB,
    float* __restrict__ Ob, int ldo, long bsO,
    int M, int C, int O,
    const float* __restrict__ s, const float* __restrict__ t,
    const float* __restrict__ gadd,
    __nv_bfloat16* __restrict__ So, int ldso)
{
    constexpr int NJ = TILEO / 32;    // 16-row B jp-tiles per warp
    constexpr int WOC = TILEO / 2;    // warp O-span
    __shared__ __align__(16) __nv_bfloat16 sAhi[128 * PITCH];
    __shared__ __align__(16) __nv_bfloat16 sAlo[128 * PITCH];
    __shared__ __align__(16) __nv_bfloat16 sBhi[TILEO * PITCH];
    __shared__ __align__(16) __nv_bfloat16 sBlo[TILEO * PITCH];

    const __nv_bfloat16* A = Ab + (long)blockIdx.z * bsA;
    const __nv_bfloat16* B = Bb + (long)blockIdx.z * bsB;
    float* Out = Ob + (long)blockIdx.z * bsO;
    const int m0 = blockIdx.y * 128, o0 = blockIdx.x * TILEO;
    const int tid = threadIdx.x, lane = tid & 31, wid = tid >> 5;
    const int wm = wid & 3, wo = wid >> 2;
    const __nv_bfloat16 zb = __float2bfloat16(0.0f);

    const uint32_t uAhi = smem_u32(sAhi), uAlo = smem_u32(sAlo);
    const uint32_t uBhi = smem_u32(sBhi), uBlo = smem_u32(sBlo);

    float acc[2][TILEO / 16][4];
#pragma unroll
    for (int i = 0; i < 2; i++)
#pragma unroll
        for (int j = 0; j < TILEO / 16; j++)
#pragma unroll
            for (int q = 0; q < 4; q++) acc[i][j][q] = 0.f;

    const int nch = (C + 31) >> 5;
    const bool fastv = ((lda & 7) == 0) && ((ldb & 7) == 0) && ((C & 7) == 0);

    for (int cc = 0; cc < nch; cc++) {
        const int kb = cc * 32;
        int vc = C - kb; if (vc > 32) vc = 32;
        const bool fast = fastv && (vc == 32);

        __syncthreads();
        if (tid < 128) {
            const int r = tid;
            const long ra = (long)(m0 + r) * lda;
            if (fast) {
                const uint4* s0 = (const uint4*)(A + ra + kb);
                const uint4* s1 = (const uint4*)(A + ra + loA + kb);
                uint4* d0 = (uint4*)(sAhi + r * PITCH);
                uint4* d1 = (uint4*)(sAlo + r * PITCH);
#pragma unroll
                for (int q = 0; q < 4; q++) { d0[q] = s0[q]; d1[q] = s1[q]; }
            } else {
                for (int j = 0; j < 32; j++) {
                    bool ok = (j < vc);
                    sAhi[r * PITCH + j] = ok ? A[ra + kb + j] : zb;
                    sAlo[r * PITCH + j] = ok ? A[ra + loA + kb + j] : zb;
                }
            }
        } else if (tid < 128 + TILEO) {
            const int r = tid - 128;
            const int o = o0 + r;
            if (o < O) {
                const long rb = (long)o * ldb;
                if (fast) {
                    const uint4* s0 = (const uint4*)(B + rb + kb);
                    const uint4* s1 = (const uint4*)(B + rb + loB + kb);
                    uint4* d0 = (uint4*)(sBhi + r * PITCH);
                    uint4* d1 = (uint4*)(sBlo + r * PITCH);
#pragma unroll
                    for (int q = 0; q < 4; q++) { d0[q] = s0[q]; d1[q] = s1[q]; }
                } else {
                    for (int j = 0; j < 32; j++) {
                        bool ok = (j < vc);
                        sBhi[r * PITCH + j] = ok ? B[rb + kb + j] : zb;
                        sBlo[r * PITCH + j] = ok ? B[rb + loB + kb + j] : zb;
                    }
                }
            } else {
                uint4 z4 = {0, 0, 0, 0};
                uint4* d0 = (uint4*)(sBhi + r * PITCH);
                uint4* d1 = (uint4*)(sBlo + r * PITCH);
#pragma unroll
                for (int q = 0; q < 4; q++) { d0[q] = z4; d1[q] = z4; }
            }
        }
        __syncthreads();

#pragma unroll
        for (int ks = 0; ks < 2; ks++) {
            const int k0 = ks * 16;
            uint32_t ah[2][4], al[2][4];
            const int arow = lane & 15;
            const int acol = k0 + ((lane >> 4) << 3);
#pragma unroll
            for (int i = 0; i < 2; i++) {
                uint32_t off = ((wm * 32 + i * 16 + arow) * PITCH + acol) * 2;
                ldsm_x4(ah[i], uAhi + off);
                ldsm_x4(al[i], uAlo + off);
            }
            const int seg = lane >> 3;
            const int brow = (lane & 7) + ((seg & 2) << 2);
            const int bcol = k0 + ((seg & 1) << 3);
#pragma unroll
            for (int jp = 0; jp < NJ; jp++) {
                uint32_t bh[4], bl[4];
                uint32_t off = ((wo * WOC + jp * 16 + brow) * PITCH + bcol) * 2;
                ldsm_x4(bh, uBhi + off);
                ldsm_x4(bl, uBlo + off);
#pragma unroll
                for (int i = 0; i < 2; i++) {
                    mma16816(acc[i][2 * jp],     ah[i], bh[0], bh[1]);
                    mma16816(acc[i][2 * jp + 1], ah[i], bh[2], bh[3]);
                    mma16816(acc[i][2 * jp],     ah[i], bl[0], bl[1]);
                    mma16816(acc[i][2 * jp + 1], ah[i], bl[2], bl[3]);
                    mma16816(acc[i][2 * jp],     al[i], bh[0], bh[1]);
                    mma16816(acc[i][2 * jp + 1], al[i], bh[2], bh[3]);
                }
            }
        }
    }

    // epilogue: fragment layout -> global, fused activation (+optional split)
    const int qrow = lane >> 2, qcol = (lane & 3) * 2;
    const int half = ldso >> 1;
    const float* xxA = (MODE == 4) ? (s + (long)blockIdx.z * M) : nullptr;
    const float* xxB = (MODE == 4) ? (t + (long)blockIdx.z * M) : nullptr;
#pragma unroll
    for (int i = 0; i < 2; i++) {
        const int mA = m0 + wm * 32 + i * 16 + qrow;
#pragma unroll
        for (int j = 0; j < TILEO / 16; j++) {
            const int o = o0 + wo * WOC + j * 8 + qcol;
#pragma unroll
            for (int q = 0; q < 4; q++) {
                const int m = mA + ((q >> 1) ? 8 : 0);
                const int oo = o + (q & 1);
                if (oo >= O) continue;
                float v = acc[i][j][q];
                if (MODE == 1) { v = s[oo] * v + t[oo]; v = v >= 0.f ? v : 0.2f * v; }
                else if (MODE == 2) {
                    v = s[oo] * (v + gadd[(m >> 11) * O + oo]) + t[oo];
                    v = v >= 0.f ? v : 0.2f * v;
                }
                else if (MODE == 3) { v = v + t[oo]; }
                else if (MODE == 4) { v = xxA[m] + xxB[oo] - 2.f * v; }
                Out[(long)m * ldo + oo] = v;
                if (So) {
                    __nv_bfloat16 h = __float2bfloat16(v);
                    So[(long)m * ldso + oo] = h;
                    So[(long)m * ldso + half + oo] =
                        __float2bfloat16(v - __bfloat162float(h));
                }
            }
        }
    }
}

// ---------------- deterministic column means ---------------------------------
__global__ void __launch_bounds__(256) colsum_part(
    const float* __restrict__ X, int ldx, float* __restrict__ msum, int C)
{
    __shared__ float sh[8][33];
    const int lane = threadIdx.x & 31, w = threadIdx.x >> 5;
    const int c = blockIdx.x * 32 + lane;
    const int base = blockIdx.y * 256;
    float a = 0.f;
    for (int r = w; r < 256; r += 8) a += X[(long)(base + r) * ldx + c];
    sh[w][lane] = a;
    __syncthreads();
    if (w == 0) {
        float sfull = 0.f;
#pragma unroll
        for (int i = 0; i < 8; i++) sfull += sh[i][lane];
        msum[blockIdx.y * C + c] = sfull;
    }
}
__global__ void colmean_fin(const float* __restrict__ msum,
                            float* __restrict__ mean, int C)
{
    int c = threadIdx.x;
    if (c >= C) return;
    float sfull = 0.f;
    for (int i = 0; i < 64; i++) sfull += msum[i * C + c];
    mean[c] = sfull * (1.f / MTOT);
}

// ---------------- fused center + split + row-norm (blockDim == C) ------------
__global__ void center_split_norm(const float* __restrict__ X, int ldx, int C,
                                  const float* __restrict__ mean,
                                  __nv_bfloat16* __restrict__ Xc,
                                  float* __restrict__ xx)
{
    __shared__ float sh[4];
    const int row = blockIdx.x, tid = threadIdx.x;
    const int lane = tid & 31, wrp = tid >> 5;
    float x = X[(long)row * ldx + tid] - mean[tid];
    __nv_bfloat16 h = __float2bfloat16(x);
    Xc[(long)row * 2 * C + tid] = h;
    Xc[(long)row * 2 * C + C + tid] = __float2bfloat16(x - __bfloat162float(h));
    float a = x * x;
#pragma unroll
    for (int off = 16; off > 0; off >>= 1) a += __shfl_down_sync(0xFFFFFFFFu, a, off);
    if (lane == 0) sh[wrp] = a;
    __syncthreads();
    if (tid == 0) {
        float tot = 0.f;
        for (int i = 0; i < (C >> 5); i++) tot += sh[i];
        xx[row] = tot;
    }
}

// ---------------- fp32 -> split bf16 [hi|lo] (weights / xyz) -----------------
__global__ void conv_split(const float* __restrict__ X, int ldx, int C, int Mrows,
                           __nv_bfloat16* __restrict__ Y)
{
    long i = (long)blockIdx.x * blockDim.x + threadIdx.x;
    long tot = (long)Mrows * C;
    if (i >= tot) return;
    int m = (int)(i / C), c = (int)(i - (long)m * C);
    float x = X[(long)m * ldx + c];
    __nv_bfloat16 h = __float2bfloat16(x);
    Y[(long)m * 2 * C + c] = h;
    Y[(long)m * 2 * C + C + c] = __float2bfloat16(x - __bfloat162float(h));
}

// ---------------- [W1 ; W2-W1] directly to split bf16 ------------------------
__global__ void prep_wc_split(const float* __restrict__ w,
                              __nv_bfloat16* __restrict__ wcb, int O, int C)
{
    int i = blockIdx.x * blockDim.x + threadIdx.x;
    if (i >= O * C) return;
    int o = i / C, c = i - o * C;
    float w1 = w[(long)o * 2 * C + c];
    float w2 = w[(long)o * 2 * C + C + c];
    __nv_bfloat16 h1b = __float2bfloat16(w1);
    wcb[(long)o * 2 * C + c] = h1b;
    wcb[(long)o * 2 * C + C + c] = __float2bfloat16(w1 - __bfloat162float(h1b));
    float d = w2 - w1;
    __nv_bfloat16 h2b = __float2bfloat16(d);
    wcb[(long)(O + o) * 2 * C + c] = h2b;
    wcb[(long)(O + o) * 2 * C + C + c] = __float2bfloat16(d - __bfloat162float(h2b));
}

// ======== 1-barrier top-20 extraction core (parity-buffered wv/wi) ==========
#define TOPK_EXTRACT(v, mv, ms, row, idxout)                                   \
    for (int itk = 0; itk < 20; itk++) {                                       \
        const int pb = itk & 1;                                                \
        float bv = mv;                                                         \
        int bidx = ms * 128 + tid;                                             \
        _Pragma("unroll")                                                      \
        for (int off = 16; off > 0; off >>= 1) {                               \
            float ov = __shfl_down_sync(0xFFFFFFFFu, bv, off);                 \
            int oi = __shfl_down_sync(0xFFFFFFFFu, bidx, off);                 \
            if (ov < bv || (ov == bv && oi < bidx)) { bv = ov; bidx = oi; }    \
        }                                                                      \
        if (lane == 0) { wv[pb][wrp] = bv; wi[pb][wrp] = bidx; }               \
        __syncthreads();                                                       \
        float fv = wv[pb][0];                                                  \
        int fi = wi[pb][0];                                                    \
        _Pragma("unroll")                                                      \
        for (int ww = 1; ww < 4; ww++)                                         \
            if (wv[pb][ww] < fv || (wv[pb][ww] == fv && wi[pb][ww] < fi)) {    \
                fv = wv[pb][ww]; fi = wi[pb][ww];                              \
            }                                                                  \
        if (tid == 0) idxout[(long)row * 20 + itk] = fi;                       \
        if ((fi & 127) == tid) {                                               \
            v[fi >> 7] = FLT_MAX;                                              \
            mv = v[0]; ms = 0;                                                 \
            _Pragma("unroll")                                                  \
            for (int i2 = 1; i2 < 16; i2++)                                    \
                if (v[i2] < mv) { mv = v[i2]; ms = i2; }                       \
        }                                                                      \
    }

// ---------------- layer-1 fused exact kNN (xyz from L2, slim smem) -----------
__global__ void __launch_bounds__(128) topk_xyz(
    const float* __restrict__ xyz, int* __restrict__ idxout)
{
    __shared__ float wv[2][4];
    __shared__ int   wi[2][4];

    const int row = blockIdx.x;
    const int b = row >> 11, n = row & 2047;
    const float* xb = xyz + (long)b * NPTS * 3;
    const int tid = threadIdx.x;
    const int lane = tid & 31, wrp = tid >> 5;

    const float xi = xb[n * 3], yi = xb[n * 3 + 1], zi = xb[n * 3 + 2];

    float v[16];
#pragma unroll
    for (int i = 0; i < 16; i++) {
        int j = i * 128 + tid;
        float dx = xb[j * 3] - xi, dy = xb[j * 3 + 1] - yi, dz = xb[j * 3 + 2] - zi;
        v[i] = dx * dx + dy * dy + dz * dz;
    }
    float mv = v[0];
    int ms = 0;
#pragma unroll
    for (int i = 1; i < 16; i++)
        if (v[i] < mv) { mv = v[i]; ms = i; }

    TOPK_EXTRACT(v, mv, ms, row, idxout)
}

// ---------------- top-20 smallest of D[row, j] (distances precomputed) -------
__global__ void __launch_bounds__(128) topk_kernel(
    const float* __restrict__ D, int* __restrict__ idxout)
{
    __shared__ float wv[2][4];
    __shared__ int   wi[2][4];

    const int row = blockIdx.x;
    const float* g = D + (long)row * NPTS;
    const int tid = threadIdx.x;
    const int lane = tid & 31, wrp = tid >> 5;

    float v[16];
#pragma unroll
    for (int i = 0; i < 16; i++) v[i] = g[i * 128 + tid];
    float mv = v[0];
    int ms = 0;
#pragma unroll
    for (int i = 1; i < 16; i++)
        if (v[i] < mv) { mv = v[i]; ms = i; }

    TOPK_EXTRACT(v, mv, ms, row, idxout)
}

// ---------------- gather-max + epilogue (+ fused split output) ---------------
__global__ void __launch_bounds__(128) edge_max_kernel(
    const float* __restrict__ YZ, int ldyz,
    const int* __restrict__ idx,
    const float* __restrict__ s,
    const float* __restrict__ t,
    float* __restrict__ out, int ldo,
    __nv_bfloat16* __restrict__ sout, int O)
{
    __shared__ int nb[20];
    int bn = blockIdx.x;
    int bbase = (bn >> 11) << 11;
    if (threadIdx.x < 20) nb[threadIdx.x] = idx[bn * 20 + threadIdx.x];
    __syncthreads();
    for (int o = threadIdx.x; o < O; o += 128) {
        float z = YZ[(long)bn * ldyz + O + o];
        float m = -FLT_MAX;
#pragma unroll
        for (int kk = 0; kk < 20; kk++) {
            float y = YZ[(long)(bbase + nb[kk]) * ldyz + o];
            m = fmaxf(m, y);
        }
        float v = s[o] * (m + z) + t[o];
        v = v >= 0.f ? v : 0.2f * v;
        out[(long)bn * ldo + o] = v;
        __nv_bfloat16 h = __float2bfloat16(v);
        sout[(long)bn * 1024 + o] = h;
        sout[(long)bn * 1024 + 512 + o] = __float2bfloat16(v - __bfloat162float(h));
    }
}

// ---------------- global max over N (coalesced) ------------------------------
__global__ void __launch_bounds__(256) maxreduce_kernel(
    const float* __restrict__ xemb, float* __restrict__ glob)
{
    __shared__ float sh[8][33];
    const int lane = threadIdx.x & 31, grp = threadIdx.x >> 5;
    const int o = blockIdx.x * 32 + lane;
    const int b = blockIdx.y;
    const float* p = xemb + (long)b * NPTS * 1024 + o;
    float m = -FLT_MAX;
    for (int n = grp; n < NPTS; n += 8) m = fmaxf(m, p[(long)n * 1024]);
    sh[grp][lane] = m;
    __syncthreads();
    if (grp == 0) {
#pragma unroll
        for (int r = 1; r < 8; r++) m = fmaxf(m, sh[r][lane]);
        glob[b * 1024 + o] = m;
    }
}

// ---------------- per-batch global-feature bias for h1 -----------------------
__global__ void gbias_kernel(const float* __restrict__ h1w,
                             const float* __restrict__ glob,
                             float* __restrict__ gb)
{
    __shared__ float gsh[1024];
    int b = blockIdx.x, o = threadIdx.x;
    for (int c = threadIdx.x; c < 1024; c += 256) gsh[c] = glob[b * 1024 + c];
    __syncthreads();
    const float* wr = h1w + (long)o * 1536 + 512;
    float acc = 0.f;
    for (int c = 0; c < 1024; c++) acc += gsh[c] * wr[c];
    gb[b * 256 + o] = acc;
}

// ---------------- host orchestration -----------------------------------------
static inline dim3 tgrid(int M, int O, int Z, int TO) {
    return dim3((O + TO - 1) / TO, (M + 127) / 128, Z);
}
static inline int cgrid(long n) { return (int)((n + 255) / 256); }

// layers 2-4: centered Gram kNN (fused dist epilogue) + YZ GEMM
static void run_edge_layer_tc(const float* X, int inoff, int C, int O,
                              const float* w, const float* s, const float* t,
                              float* pG, float* pxx, int* pidx,
                              float* pmean, float* pmsum,
                              __nv_bfloat16* pXb, __nv_bfloat16* pXc,
                              __nv_bfloat16* pWb, float* pYZ,
                              float* outcol, int outoff)
{
    colsum_part<<<dim3(C / 32, 64), 256>>>(X, 512, pmsum, C);
    colmean_fin<<<1, 128>>>(pmsum, pmean, C);
    center_split_norm<<<MTOT, C>>>(X, 512, C, pmean, pXc, pxx);
    prep_wc_split<<<cgrid(O * C), 256>>>(w, pWb, O, C);
    // Gram with fused distance epilogue: G[m,o] = xx[m] + xx[o] - 2*dot
    gemm_mma<4, 128><<<tgrid(NPTS, NPTS, BATCH, 128), 256>>>(
        pXc, 2 * C, (long)NPTS * 2 * C, C, pXc, 2 * C, (long)NPTS * 2 * C, C,
        pG, NPTS, (long)NPTS * NPTS, NPTS, C, NPTS,
        pxx, pxx, nullptr, nullptr, 0);
    topk_kernel<<<MTOT, 128>>>(pG, pidx);
    // YZ = X @ [W1; W2-W1]^T, A = fused xcat split at column inoff
    if (2 * O >= 512)
        gemm_mma<0, 128><<<tgrid(MTOT, 2 * O, 1, 128), 256>>>(
            pXb + inoff, 1024, 0L, 512, pWb, 2 * C, 0L, C, pYZ, 2 * O, 0L,
            MTOT, C, 2 * O, nullptr, nullptr, nullptr, nullptr, 0);
    else
        gemm_mma<0, 64><<<tgrid(MTOT, 2 * O, 1, 64), 256>>>(
            pXb + inoff, 1024, 0L, 512, pWb, 2 * C, 0L, C, pYZ, 2 * O, 0L,
            MTOT, C, 2 * O, nullptr, nullptr, nullptr, nullptr, 0);
    edge_max_kernel<<<MTOT, 128>>>(pYZ, 2 * O, pidx, s, t,
                                   outcol, 512, pXb + outoff, O);
}

extern "C" void kernel_launch(void* const* d_in, const int* in_sizes, int n_in,
                              void* d_out, int out_size)
{
    const float* xyz    = (const float*)d_in[0];
    const float* ec1_w  = (const float*)d_in[1];
    const float* ec1_s  = (const float*)d_in[2];
    const float* ec1_t  = (const float*)d_in[3];
    const float* ec2_w  = (const float*)d_in[4];
    const float* ec2_s  = (const float*)d_in[5];
    const float* ec2_t  = (const float*)d_in[6];
    const float* ec3_w  = (const float*)d_in[7];
    const float* ec3_s  = (const float*)d_in[8];
    const float* ec3_t  = (const float*)d_in[9];
    const float* ec4_w  = (const float*)d_in[10];
    const float* ec4_s  = (const float*)d_in[11];
    const float* ec4_t  = (const float*)d_in[12];
    const float* fuse_w = (const float*)d_in[13];
    const float* fuse_s = (const float*)d_in[14];
    const float* fuse_t = (const float*)d_in[15];
    const float* emb_w  = (const float*)d_in[16];
    const float* emb_s  = (const float*)d_in[17];
    const float* emb_t  = (const float*)d_in[18];
    const float* h1_w   = (const float*)d_in[19];
    const float* h1_s   = (const float*)d_in[20];
    const float* h1_t   = (const float*)d_in[21];
    const float* h2_w   = (const float*)d_in[22];
    const float* h2_s   = (const float*)d_in[23];
    const float* h2_t   = (const float*)d_in[24];
    const float* h3_w   = (const float*)d_in[25];
    const float* h3_b   = (const float*)d_in[26];
    float* out = (float*)d_out;

    float *pG, *pxcat, *pYZ, *pxloc, *pxemb, *ph1, *ph2, *pxx, *pglob, *pgb;
    float *pmean, *pmsum;
    __nv_bfloat16 *pXb, *pXb2, *pXc, *pWb;
    int* pidx;
    cudaGetSymbolAddress((void**)&pG, g_G);
    cudaGetSymbolAddress((void**)&pxcat, g_xcat);
    cudaGetSymbolAddress((void**)&pYZ, g_YZ);
    cudaGetSymbolAddress((void**)&pxloc, g_xlocal);
    cudaGetSymbolAddress((void**)&pxemb, g_xemb);
    cudaGetSymbolAddress((void**)&ph1, g_h1);
    cudaGetSymbolAddress((void**)&ph2, g_h2);
    cudaGetSymbolAddress((void**)&pxx, g_xx);
    cudaGetSymbolAddress((void**)&pglob, g_glob);
    cudaGetSymbolAddress((void**)&pgb, g_gbias);
    cudaGetSymbolAddress((void**)&pmean, g_mean);
    cudaGetSymbolAddress((void**)&pmsum, g_msum);
    cudaGetSymbolAddress((void**)&pXb, g_Xb);
    cudaGetSymbolAddress((void**)&pXb2, g_Xb2);
    cudaGetSymbolAddress((void**)&pXc, g_Xc);
    cudaGetSymbolAddress((void**)&pWb, g_Wb);
    cudaGetSymbolAddress((void**)&pidx, g_idx);

    // ---- layer 1: exact fused kNN on xyz; YZ from xyz split (C=3) -----------
    conv_split<<<cgrid((long)MTOT * 3), 256>>>(xyz, 3, 3, MTOT, pXc);
    prep_wc_split<<<cgrid(64 * 3), 256>>>(ec1_w, pWb, 64, 3);
    gemm_mma<0, 64><<<tgrid(MTOT, 128, 1, 64), 256>>>(
        pXc, 6, 0L, 3, pWb, 6, 0L, 3, pYZ, 128, 0L,
        MTOT, 3, 128, nullptr, nullptr, nullptr, nullptr, 0);
    topk_xyz<<<MTOT, 128>>>(xyz, pidx);
    edge_max_kernel<<<MTOT, 128>>>(pYZ, 128, pidx, ec1_s, ec1_t,
                                   pxcat + 0, 512, pXb + 0, 64);

    // ---- layers 2-4 (inputs read from xcat fp32 + fused xcat split) ---------
    run_edge_layer_tc(pxcat + 0,   0,   64,  64,  ec2_w, ec2_s, ec2_t,
                      pG, pxx, pidx, pmean, pmsum, pXb, pXc, pWb, pYZ,
                      pxcat + 64, 64);
    run_edge_layer_tc(pxcat + 64,  64,  64,  128, ec3_w, ec3_s, ec3_t,
                      pG, pxx, pidx, pmean, pmsum, pXb, pXc, pWb, pYZ,
                      pxcat + 128, 128);
    run_edge_layer_tc(pxcat + 128, 128, 128, 256, ec4_w, ec4_s, ec4_t,
                      pG, pxx, pidx, pmean, pmsum, pXb, pXc, pWb, pYZ,
                      pxcat + 256, 256);

    // fuse: (16384,512) -> 512, lrelu; split output fused into epilogue
    conv_split<<<cgrid(512L * 512), 256>>>(fuse_w, 512, 512, 512, pWb);
    gemm_mma<1, 128><<<tgrid(MTOT, 512, 1, 128), 256>>>(
        pXb, 1024, 0L, 512, pWb, 1024, 0L, 512, pxloc, 512, 0L,
        MTOT, 512, 512, fuse_s, fuse_t, nullptr, pXb2, 1024);
    // emb: 512 -> 1024, lrelu (consumes fused split)
    conv_split<<<cgrid(1024L * 512), 256>>>(emb_w, 512, 512, 1024, pWb);
    gemm_mma<1, 128><<<tgrid(MTOT, 1024, 1, 128), 256>>>(
        pXb2, 1024, 0L, 512, pWb, 1024, 0L, 512, pxemb, 1024, 0L,
        MTOT, 512, 1024, emb_s, emb_t, nullptr, nullptr, 0);
    // global max over N + per-batch bias via h1_w[:,512:]
    maxreduce_kernel<<<dim3(32, BATCH), 256>>>(pxemb, pglob);
    gbias_kernel<<<BATCH, 256>>>(h1_w, pglob, pgb);
    // h1: 512 -> 256 with per-batch gadd, lrelu; split out -> pXb
    conv_split<<<cgrid(256L * 512), 256>>>(h1_w, 1536, 512, 256, pWb);
    gemm_mma<2, 128><<<tgrid(MTOT, 256, 1, 128), 256>>>(
        pXb2, 1024, 0L, 512, pWb, 1024, 0L, 512, ph1, 256, 0L,
        MTOT, 512, 256, h1_s, h1_t, pgb, pXb, 512);
    // h2: 256 -> 256, lrelu; split out -> pXb2
    conv_split<<<cgrid(256L * 256), 256>>>(h2_w, 256, 256, 256, pWb);
    gemm_mma<1, 128><<<tgrid(MTOT, 256, 1, 128), 256>>>(
        pXb, 512, 0L, 256, pWb, 512, 0L, 256, ph2, 256, 0L,
        MTOT, 256, 256, h2_s, h2_t, nullptr, pXb2, 512);
    // h3: 256 -> 13, +bias -> d_out
    conv_split<<<cgrid(13L * 256), 256>>>(h3_w, 256, 256, 13, pWb);
    gemm_mma<3, 64><<<tgrid(MTOT, 13, 1, 64), 256>>>(
        pXb2, 512, 0L, 256, pWb, 512, 0L, 256, out, 13, 0L,
        MTOT, 256, 13, nullptr, h3_b, nullptr, nullptr, 0);
}

// round 15
// speedup vs baseline: 1.5924x; 1.0636x over previous
#include <cuda_runtime.h>
#include <cuda_bf16.h>
#include <float.h>
#include <stdint.h>

#define NPTS 2048
#define BATCH 8
#define MTOT (BATCH * NPTS)

// ---------------- scratch (device globals; no runtime allocation) ------------
__device__ float g_G[(size_t)BATCH * NPTS * NPTS];   // 128 MB dist scratch
__device__ float g_xcat[(size_t)MTOT * 512];
__device__ float g_YZ[(size_t)MTOT * 512];
__device__ float g_xlocal[(size_t)MTOT * 512];
__device__ float g_xemb[(size_t)MTOT * 1024];
__device__ float g_h1[(size_t)MTOT * 256];
__device__ float g_h2[(size_t)MTOT * 256];
__device__ float g_xx[MTOT];
__device__ int   g_idx[MTOT * 20];
__device__ float g_glob[BATCH * 1024];
__device__ float g_gbias[BATCH * 256];
__device__ float g_mean[512];
__device__ float g_msum[64 * 512];
__device__ __nv_bfloat16 g_Xb[(size_t)MTOT * 1024];  // xcat split [hi512|lo512]
__device__ __nv_bfloat16 g_Xb2[(size_t)MTOT * 1024]; // split scratch B
__device__ __nv_bfloat16 g_Xc[(size_t)MTOT * 256];   // centered split / xyz split
__device__ __nv_bfloat16 g_Wb[(size_t)4 * 1024 * 1024]; // all split weights

// weight-prep offsets into g_Wb (elements)
#define OFF_EC1  0
#define OFF_EC2  1024
#define OFF_EC3  20480
#define OFF_EC4  57344
#define OFF_FUSE 192512
#define OFF_EMB  720896
#define OFF_H1   1769472
#define OFF_H2   2031616
#define OFF_H3   2162688

// ---------------- warp-mma helpers -------------------------------------------
__device__ __forceinline__ uint32_t smem_u32(const void* p) {
    uint32_t a;
    asm("{ .reg .u64 t; cvta.to.shared.u64 t, %1; cvt.u32.u64 %0, t; }"
        : "=r"(a) : "l"(p));
    return a;
}
__device__ __forceinline__ void ldsm_x4(uint32_t* r, uint32_t addr) {
    asm volatile("ldmatrix.sync.aligned.m8n8.x4.shared.b16 {%0,%1,%2,%3}, [%4];"
                 : "=r"(r[0]), "=r"(r[1]), "=r"(r[2]), "=r"(r[3]) : "r"(addr));
}
__device__ __forceinline__ void mma16816(float* c, const uint32_t* a,
                                         uint32_t b0, uint32_t b1) {
    asm volatile(
        "mma.sync.aligned.m16n8k16.row.col.f32.bf16.bf16.f32 "
        "{%0,%1,%2,%3}, {%4,%5,%6,%7}, {%8,%9}, {%0,%1,%2,%3};"
        : "+f"(c[0]), "+f"(c[1]), "+f"(c[2]), "+f"(c[3])
        : "r"(a[0]), "r"(a[1]), "r"(a[2]), "r"(a[3]), "r"(b0), "r"(b1));
}
#define CPA16(dst, src) \
    asm volatile("cp.async.cg.shared.global [%0], [%1], 16;" :: "r"(dst), "l"(src))
#define CPA_COMMIT() asm volatile("cp.async.commit_group;" ::: "memory")

#define PITCH 40   // smem row pitch in bf16 (80B: conflict-free ldmatrix)

// ---------------- split-bf16 tensor GEMM: out[m,o] = sum_c X[m,c]*W[o,c] -----
// A rows: hi at [c], lo at [loA + c]. B rows: hi at [c], lo at [loB + c].
// Accumulate hi*hi + hi*lo + lo*hi in fp32 via mma.sync.
// 256 threads. CTA tile 128(M) x TILEO(O); warp tile 32 x TILEO/2.
// PIPE: cp.async 2-stage pipeline; requires C%32==0, lda/ldb%8==0, O%TILEO==0.
// Optional So/ldso: also emit split-bf16 [hi|lo] (lo at +ldso/2) of output.
// MODE 0: raw  1: lrelu(s*v+t)  2: lrelu(s*(v+gadd[b,o])+t)  3: v+t[o]
// MODE 4: dist epilogue v = s[z*M+m] + t[z*M+oo] - 2v  (Gram -> distances)
template <int MODE, int TILEO, bool PIPE>
__global__ void __launch_bounds__(256) gemm_mma(
    const __nv_bfloat16* __restrict__ Ab, int lda, long bsA, int loA,
    const __nv_bfloat16* __restrict__ Bb, int ldb, long bsB, int loB,
    float* __restrict__ Ob, int ldo, long bsO,
    int M, int C, int O,
    const float* __restrict__ s, const float* __restrict__ t,
    const float* __restrict__ gadd,
    __nv_bfloat16* __restrict__ So, int ldso)
{
    constexpr int NBUF = PIPE ? 2 : 1;
    constexpr int NJ = TILEO / 32;    // 16-row B jp-tiles per warp
    constexpr int WOC = TILEO / 2;    // warp O-span
    constexpr uint32_t szA = 128 * PITCH * 2;    // bytes per A half-buffer
    constexpr uint32_t szB = TILEO * PITCH * 2;  // bytes per B half-buffer

    extern __shared__ __align__(16) unsigned char dynraw[];
    __nv_bfloat16* sAhiP = (__nv_bfloat16*)dynraw;
    __nv_bfloat16* sAloP = sAhiP + NBUF * 128 * PITCH;
    __nv_bfloat16* sBhiP = sAloP + NBUF * 128 * PITCH;
    __nv_bfloat16* sBloP = sBhiP + NBUF * TILEO * PITCH;
    const uint32_t uAhi = smem_u32(sAhiP), uAlo = smem_u32(sAloP);
    const uint32_t uBhi = smem_u32(sBhiP), uBlo = smem_u32(sBloP);

    const __nv_bfloat16* A = Ab + (long)blockIdx.z * bsA;
    const __nv_bfloat16* B = Bb + (long)blockIdx.z * bsB;
    float* Out = Ob + (long)blockIdx.z * bsO;
    const int m0 = blockIdx.y * 128, o0 = blockIdx.x * TILEO;
    const int tid = threadIdx.x, lane = tid & 31, wid = tid >> 5;
    const int wm = wid & 3, wo = wid >> 2;
    const __nv_bfloat16 zb = __float2bfloat16(0.0f);

    float acc[2][TILEO / 16][4];
#pragma unroll
    for (int i = 0; i < 2; i++)
#pragma unroll
        for (int j = 0; j < TILEO / 16; j++)
#pragma unroll
            for (int q = 0; q < 4; q++) acc[i][j][q] = 0.f;

    const int nch = (C + 31) >> 5;
    const bool fastv = ((lda & 7) == 0) && ((ldb & 7) == 0) && ((C & 7) == 0);

    // ---- async stage: chunk cc -> buffer bf (PIPE only) ----
    auto stage_async = [&](int cc, int bf) {
        const int kb = cc * 32;
        // A: 1024 txns, 4 per thread: row = tid>>1, half = tid&1, subs 0..3
        {
            const int r = tid >> 1, half = tid & 1;
            const __nv_bfloat16* src =
                A + (long)(m0 + r) * lda + (half ? loA : 0) + kb;
            const uint32_t dst =
                (half ? uAlo : uAhi) + bf * szA + r * (PITCH * 2);
#pragma unroll
            for (int q2 = 0; q2 < 4; q2++)
                CPA16(dst + q2 * 16, src + q2 * 8);
        }
        // B: TILEO*8 txns, TILEO/32 per thread
        constexpr int BT = TILEO / 32;
#pragma unroll
        for (int q2 = 0; q2 < BT; q2++) {
            const int idx = tid * BT + q2;
            const int r = idx >> 3, half = (idx >> 2) & 1, sub = idx & 3;
            const __nv_bfloat16* src =
                B + (long)(o0 + r) * ldb + (half ? loB : 0) + kb + sub * 8;
            const uint32_t dst =
                (half ? uBlo : uBhi) + bf * szB + (r * PITCH + sub * 8) * 2;
            CPA16(dst, src);
        }
    };

    if (PIPE) { stage_async(0, 0); CPA_COMMIT(); }

    for (int cc = 0; cc < nch; cc++) {
        int buf;
        if (PIPE) {
            if (cc + 1 < nch) {
                stage_async(cc + 1, (cc + 1) & 1);
                CPA_COMMIT();
                asm volatile("cp.async.wait_group 1;" ::: "memory");
            } else {
                asm volatile("cp.async.wait_group 0;" ::: "memory");
            }
            __syncthreads();
            buf = cc & 1;
        } else {
            const int kb = cc * 32;
            int vc = C - kb; if (vc > 32) vc = 32;
            const bool fast = fastv && (vc == 32);
            __syncthreads();
            if (tid < 128) {
                const int r = tid;
                const long ra = (long)(m0 + r) * lda;
                if (fast) {
                    const uint4* s0 = (const uint4*)(A + ra + kb);
                    const uint4* s1 = (const uint4*)(A + ra + loA + kb);
                    uint4* d0 = (uint4*)(sAhiP + r * PITCH);
                    uint4* d1 = (uint4*)(sAloP + r * PITCH);
#pragma unroll
                    for (int q = 0; q < 4; q++) { d0[q] = s0[q]; d1[q] = s1[q]; }
                } else {
                    for (int j = 0; j < 32; j++) {
                        bool ok = (j < vc);
                        sAhiP[r * PITCH + j] = ok ? A[ra + kb + j] : zb;
                        sAloP[r * PITCH + j] = ok ? A[ra + loA + kb + j] : zb;
                    }
                }
            } else if (tid < 128 + TILEO) {
                const int r = tid - 128;
                const int o = o0 + r;
                if (o < O) {
                    const long rb = (long)o * ldb;
                    if (fast) {
                        const uint4* s0 = (const uint4*)(B + rb + kb);
                        const uint4* s1 = (const uint4*)(B + rb + loB + kb);
                        uint4* d0 = (uint4*)(sBhiP + r * PITCH);
                        uint4* d1 = (uint4*)(sBloP + r * PITCH);
#pragma unroll
                        for (int q = 0; q < 4; q++) { d0[q] = s0[q]; d1[q] = s1[q]; }
                    } else {
                        for (int j = 0; j < 32; j++) {
                            bool ok = (j < vc);
                            sBhiP[r * PITCH + j] = ok ? B[rb + kb + j] : zb;
                            sBloP[r * PITCH + j] = ok ? B[rb + loB + kb + j] : zb;
                        }
                    }
                } else {
                    uint4 z4 = {0, 0, 0, 0};
                    uint4* d0 = (uint4*)(sBhiP + r * PITCH);
                    uint4* d1 = (uint4*)(sBloP + r * PITCH);
#pragma unroll
                    for (int q = 0; q < 4; q++) { d0[q] = z4; d1[q] = z4; }
                }
            }
            __syncthreads();
            buf = 0;
        }

#pragma unroll
        for (int ks = 0; ks < 2; ks++) {
            const int k0 = ks * 16;
            uint32_t ah[2][4], al[2][4];
            const int arow = lane & 15;
            const int acol = k0 + ((lane >> 4) << 3);
#pragma unroll
            for (int i = 0; i < 2; i++) {
                uint32_t off = buf * szA + ((wm * 32 + i * 16 + arow) * PITCH + acol) * 2;
                ldsm_x4(ah[i], uAhi + off);
                ldsm_x4(al[i], uAlo + off);
            }
            const int seg = lane >> 3;
            const int brow = (lane & 7) + ((seg & 2) << 2);
            const int bcol = k0 + ((seg & 1) << 3);
#pragma unroll
            for (int jp = 0; jp < NJ; jp++) {
                uint32_t bh[4], bl[4];
                uint32_t off = buf * szB + ((wo * WOC + jp * 16 + brow) * PITCH + bcol) * 2;
                ldsm_x4(bh, uBhi + off);
                ldsm_x4(bl, uBlo + off);
#pragma unroll
                for (int i = 0; i < 2; i++) {
                    mma16816(acc[i][2 * jp],     ah[i], bh[0], bh[1]);
                    mma16816(acc[i][2 * jp + 1], ah[i], bh[2], bh[3]);
                    mma16816(acc[i][2 * jp],     ah[i], bl[0], bl[1]);
                    mma16816(acc[i][2 * jp + 1], ah[i], bl[2], bl[3]);
                    mma16816(acc[i][2 * jp],     al[i], bh[0], bh[1]);
                    mma16816(acc[i][2 * jp + 1], al[i], bh[2], bh[3]);
                }
            }
        }
        if (PIPE) __syncthreads();   // protect buffer reuse next iteration
    }

    // epilogue: fragment layout -> global, fused activation (+optional split)
    const int qrow = lane >> 2, qcol = (lane & 3) * 2;
    const int half = ldso >> 1;
    const float* xxA = (MODE == 4) ? (s + (long)blockIdx.z * M) : nullptr;
    const float* xxB = (MODE == 4) ? (t + (long)blockIdx.z * M) : nullptr;
#pragma unroll
    for (int i = 0; i < 2; i++) {
        const int mA = m0 + wm * 32 + i * 16 + qrow;
#pragma unroll
        for (int j = 0; j < TILEO / 16; j++) {
            const int o = o0 + wo * WOC + j * 8 + qcol;
#pragma unroll
            for (int q = 0; q < 4; q++) {
                const int m = mA + ((q >> 1) ? 8 : 0);
                const int oo = o + (q & 1);
                if (oo >= O) continue;
                float v = acc[i][j][q];
                if (MODE == 1) { v = s[oo] * v + t[oo]; v = v >= 0.f ? v : 0.2f * v; }
                else if (MODE == 2) {
                    v = s[oo] * (v + gadd[(m >> 11) * O + oo]) + t[oo];
                    v = v >= 0.f ? v : 0.2f * v;
                }
                else if (MODE == 3) { v = v + t[oo]; }
                else if (MODE == 4) { v = xxA[m] + xxB[oo] - 2.f * v; }
                Out[(long)m * ldo + oo] = v;
                if (So) {
                    __nv_bfloat16 h = __float2bfloat16(v);
                    So[(long)m * ldso + oo] = h;
                    So[(long)m * ldso + half + oo] =
                        __float2bfloat16(v - __bfloat162float(h));
                }
            }
        }
    }
}

static inline int gsmem(int TILEO, bool PIPE) {
    return (PIPE ? 2 : 1) * (128 + TILEO) * PITCH * 2 * 2;
}

// ---------------- deterministic column means ---------------------------------
__global__ void __launch_bounds__(256) colsum_part(
    const float* __restrict__ X, int ldx, float* __restrict__ msum, int C)
{
    __shared__ float sh[8][33];
    const int lane = threadIdx.x & 31, w = threadIdx.x >> 5;
    const int c = blockIdx.x * 32 + lane;
    const int base = blockIdx.y * 256;
    float a = 0.f;
    for (int r = w; r < 256; r += 8) a += X[(long)(base + r) * ldx + c];
    sh[w][lane] = a;
    __syncthreads();
    if (w == 0) {
        float sfull = 0.f;
#pragma unroll
        for (int i = 0; i < 8; i++) sfull += sh[i][lane];
        msum[blockIdx.y * C + c] = sfull;
    }
}
__global__ void colmean_fin(const float* __restrict__ msum,
                            float* __restrict__ mean, int C)
{
    int c = threadIdx.x;
    if (c >= C) return;
    float sfull = 0.f;
    for (int i = 0; i < 64; i++) sfull += msum[i * C + c];
    mean[c] = sfull * (1.f / MTOT);
}

// ---------------- fused center + split + row-norm (blockDim == C) ------------
__global__ void center_split_norm(const float* __restrict__ X, int ldx, int C,
                                  const float* __restrict__ mean,
                                  __nv_bfloat16* __restrict__ Xc,
                                  float* __restrict__ xx)
{
    __shared__ float sh[4];
    const int row = blockIdx.x, tid = threadIdx.x;
    const int lane = tid & 31, wrp = tid >> 5;
    float x = X[(long)row * ldx + tid] - mean[tid];
    __nv_bfloat16 h = __float2bfloat16(x);
    Xc[(long)row * 2 * C + tid] = h;
    Xc[(long)row * 2 * C + C + tid] = __float2bfloat16(x - __bfloat162float(h));
    float a = x * x;
#pragma unroll
    for (int off = 16; off > 0; off >>= 1) a += __shfl_down_sync(0xFFFFFFFFu, a, off);
    if (lane == 0) sh[wrp] = a;
    __syncthreads();
    if (tid == 0) {
        float tot = 0.f;
        for (int i = 0; i < (C >> 5); i++) tot += sh[i];
        xx[row] = tot;
    }
}

// ---------------- fp32 -> split bf16 [hi|lo] (weights / xyz) -----------------
__global__ void conv_split(const float* __restrict__ X, int ldx, int C, int Mrows,
                           __nv_bfloat16* __restrict__ Y)
{
    long i = (long)blockIdx.x * blockDim.x + threadIdx.x;
    long tot = (long)Mrows * C;
    if (i >= tot) return;
    int m = (int)(i / C), c = (int)(i - (long)m * C);
    float x = X[(long)m * ldx + c];
    __nv_bfloat16 h = __float2bfloat16(x);
    Y[(long)m * 2 * C + c] = h;
    Y[(long)m * 2 * C + C + c] = __float2bfloat16(x - __bfloat162float(h));
}

// ---------------- [W1 ; W2-W1] directly to split bf16 ------------------------
__global__ void prep_wc_split(const float* __restrict__ w,
                              __nv_bfloat16* __restrict__ wcb, int O, int C)
{
    int i = blockIdx.x * blockDim.x + threadIdx.x;
    if (i >= O * C) return;
    int o = i / C, c = i - o * C;
    float w1 = w[(long)o * 2 * C + c];
    float w2 = w[(long)o * 2 * C + C + c];
    __nv_bfloat16 h1b = __float2bfloat16(w1);
    wcb[(long)o * 2 * C + c] = h1b;
    wcb[(long)o * 2 * C + C + c] = __float2bfloat16(w1 - __bfloat162float(h1b));
    float d = w2 - w1;
    __nv_bfloat16 h2b = __float2bfloat16(d);
    wcb[(long)(O + o) * 2 * C + c] = h2b;
    wcb[(long)(O + o) * 2 * C + C + c] = __float2bfloat16(d - __bfloat162float(h2b));
}

// ======== 1-barrier top-20 extraction core (parity-buffered wv/wi) ==========
#define TOPK_EXTRACT(v, mv, ms, row, idxout)                                   \
    for (int itk = 0; itk < 20; itk++) {                                       \
        const int pb = itk & 1;                                                \
        float bv = mv;                                                         \
        int bidx = ms * 128 + tid;                                             \
        _Pragma("unroll")                                                      \
        for (int off = 16; off > 0; off >>= 1) {                               \
            float ov = __shfl_down_sync(0xFFFFFFFFu, bv, off);                 \
            int oi = __shfl_down_sync(0xFFFFFFFFu, bidx, off);                 \
            if (ov < bv || (ov == bv && oi < bidx)) { bv = ov; bidx = oi; }    \
        }                                                                      \
        if (lane == 0) { wv[pb][wrp] = bv; wi[pb][wrp] = bidx; }               \
        __syncthreads();                                                       \
        float fv = wv[pb][0];                                                  \
        int fi = wi[pb][0];                                                    \
        _Pragma("unroll")                                                      \
        for (int ww = 1; ww < 4; ww++)                                         \
            if (wv[pb][ww] < fv || (wv[pb][ww] == fv && wi[pb][ww] < fi)) {    \
                fv = wv[pb][ww]; fi = wi[pb][ww];                              \
            }                                                                  \
        if (tid == 0) idxout[(long)row * 20 + itk] = fi;                       \
        if ((fi & 127) == tid) {                                               \
            v[fi >> 7] = FLT_MAX;                                              \
            mv = v[0]; ms = 0;                                                 \
            _Pragma("unroll")                                                  \
            for (int i2 = 1; i2 < 16; i2++)                                    \
                if (v[i2] < mv) { mv = v[i2]; ms = i2; }                       \
        }                                                                      \
    }

// ---------------- layer-1 fused exact kNN (xyz from L2, slim smem) -----------
__global__ void __launch_bounds__(128) topk_xyz(
    const float* __restrict__ xyz, int* __restrict__ idxout)
{
    __shared__ float wv[2][4];
    __shared__ int   wi[2][4];

    const int row = blockIdx.x;
    const int b = row >> 11, n = row & 2047;
    const float* xb = xyz + (long)b * NPTS * 3;
    const int tid = threadIdx.x;
    const int lane = tid & 31, wrp = tid >> 5;

    const float xi = xb[n * 3], yi = xb[n * 3 + 1], zi = xb[n * 3 + 2];

    float v[16];
#pragma unroll
    for (int i = 0; i < 16; i++) {
        int j = i * 128 + tid;
        float dx = xb[j * 3] - xi, dy = xb[j * 3 + 1] - yi, dz = xb[j * 3 + 2] - zi;
        v[i] = dx * dx + dy * dy + dz * dz;
    }
    float mv = v[0];
    int ms = 0;
#pragma unroll
    for (int i = 1; i < 16; i++)
        if (v[i] < mv) { mv = v[i]; ms = i; }

    TOPK_EXTRACT(v, mv, ms, row, idxout)
}

// ---------------- top-20 smallest of D[row, j] (distances precomputed) -------
__global__ void __launch_bounds__(128) topk_kernel(
    const float* __restrict__ D, int* __restrict__ idxout)
{
    __shared__ float wv[2][4];
    __shared__ int   wi[2][4];

    const int row = blockIdx.x;
    const float* g = D + (long)row * NPTS;
    const int tid = threadIdx.x;
    const int lane = tid & 31, wrp = tid >> 5;

    float v[16];
#pragma unroll
    for (int i = 0; i < 16; i++) v[i] = g[i * 128 + tid];
    float mv = v[0];
    int ms = 0;
#pragma unroll
    for (int i = 1; i < 16; i++)
        if (v[i] < mv) { mv = v[i]; ms = i; }

    TOPK_EXTRACT(v, mv, ms, row, idxout)
}

// ---------------- gather-max + epilogue (+ fused split output) ---------------
__global__ void __launch_bounds__(128) edge_max_kernel(
    const float* __restrict__ YZ, int ldyz,
    const int* __restrict__ idx,
    const float* __restrict__ s,
    const float* __restrict__ t,
    float* __restrict__ out, int ldo,
    __nv_bfloat16* __restrict__ sout, int O)
{
    __shared__ int nb[20];
    int bn = blockIdx.x;
    int bbase = (bn >> 11) << 11;
    if (threadIdx.x < 20) nb[threadIdx.x] = idx[bn * 20 + threadIdx.x];
    __syncthreads();
    for (int o = threadIdx.x; o < O; o += 128) {
        float z = YZ[(long)bn * ldyz + O + o];
        float m = -FLT_MAX;
#pragma unroll
        for (int kk = 0; kk < 20; kk++) {
            float y = YZ[(long)(bbase + nb[kk]) * ldyz + o];
            m = fmaxf(m, y);
        }
        float v = s[o] * (m + z) + t[o];
        v = v >= 0.f ? v : 0.2f * v;
        out[(long)bn * ldo + o] = v;
        __nv_bfloat16 h = __float2bfloat16(v);
        sout[(long)bn * 1024 + o] = h;
        sout[(long)bn * 1024 + 512 + o] = __float2bfloat16(v - __bfloat162float(h));
    }
}

// ---------------- global max over N (coalesced) ------------------------------
__global__ void __launch_bounds__(256) maxreduce_kernel(
    const float* __restrict__ xemb, float* __restrict__ glob)
{
    __shared__ float sh[8][33];
    const int lane = threadIdx.x & 31, grp = threadIdx.x >> 5;
    const int o = blockIdx.x * 32 + lane;
    const int b = blockIdx.y;
    const float* p = xemb + (long)b * NPTS * 1024 + o;
    float m = -FLT_MAX;
    for (int n = grp; n < NPTS; n += 8) m = fmaxf(m, p[(long)n * 1024]);
    sh[grp][lane] = m;
    __syncthreads();
    if (grp == 0) {
#pragma unroll
        for (int r = 1; r < 8; r++) m = fmaxf(m, sh[r][lane]);
        glob[b * 1024 + o] = m;
    }
}

// ---------------- per-batch global-feature bias for h1 -----------------------
__global__ void gbias_kernel(const float* __restrict__ h1w,
                             const float* __restrict__ glob,
                             float* __restrict__ gb)
{
    __shared__ float gsh[1024];
    int b = blockIdx.x, o = threadIdx.x;
    for (int c = threadIdx.x; c < 1024; c += 256) gsh[c] = glob[b * 1024 + c];
    __syncthreads();
    const float* wr = h1w + (long)o * 1536 + 512;
    float acc = 0.f;
    for (int c = 0; c < 1024; c++) acc += gsh[c] * wr[c];
    gb[b * 256 + o] = acc;
}

// ---------------- host orchestration -----------------------------------------
static inline dim3 tgrid(int M, int O, int Z, int TO) {
    return dim3((O + TO - 1) / TO, (M + 127) / 128, Z);
}
static inline int cgrid(long n) { return (int)((n + 255) / 256); }

// layers 2-4: centered Gram kNN (fused dist epilogue) + YZ GEMM
static void run_edge_layer_tc(const float* X, int inoff, int C, int O,
                              const __nv_bfloat16* wsplit,
                              const float* s, const float* t,
                              float* pG, float* pxx, int* pidx,
                              float* pmean, float* pmsum,
                              __nv_bfloat16* pXb, __nv_bfloat16* pXc,
                              float* pYZ, float* outcol, int outoff)
{
    colsum_part<<<dim3(C / 32, 64), 256>>>(X, 512, pmsum, C);
    colmean_fin<<<1, 128>>>(pmsum, pmean, C);
    center_split_norm<<<MTOT, C>>>(X, 512, C, pmean, pXc, pxx);
    // Gram with fused distance epilogue (PIPE)
    gemm_mma<4, 128, true><<<tgrid(NPTS, NPTS, BATCH, 128), 256, gsmem(128, true)>>>(
        pXc, 2 * C, (long)NPTS * 2 * C, C, pXc, 2 * C, (long)NPTS * 2 * C, C,
        pG, NPTS, (long)NPTS * NPTS, NPTS, C, NPTS,
        pxx, pxx, nullptr, nullptr, 0);
    topk_kernel<<<MTOT, 128>>>(pG, pidx);
    // YZ = X @ [W1; W2-W1]^T (PIPE; O'=2O is 128/256/512, all % TILEO == 0)
    if (2 * O >= 512)
        gemm_mma<0, 128, true><<<tgrid(MTOT, 2 * O, 1, 128), 256, gsmem(128, true)>>>(
            pXb + inoff, 1024, 0L, 512, wsplit, 2 * C, 0L, C, pYZ, 2 * O, 0L,
            MTOT, C, 2 * O, nullptr, nullptr, nullptr, nullptr, 0);
    else
        gemm_mma<0, 64, true><<<tgrid(MTOT, 2 * O, 1, 64), 256, gsmem(64, true)>>>(
            pXb + inoff, 1024, 0L, 512, wsplit, 2 * C, 0L, C, pYZ, 2 * O, 0L,
            MTOT, C, 2 * O, nullptr, nullptr, nullptr, nullptr, 0);
    edge_max_kernel<<<MTOT, 128>>>(pYZ, 2 * O, pidx, s, t,
                                   outcol, 512, pXb + outoff, O);
}

extern "C" void kernel_launch(void* const* d_in, const int* in_sizes, int n_in,
                              void* d_out, int out_size)
{
    const float* xyz    = (const float*)d_in[0];
    const float* ec1_w  = (const float*)d_in[1];
    const float* ec1_s  = (const float*)d_in[2];
    const float* ec1_t  = (const float*)d_in[3];
    const float* ec2_w  = (const float*)d_in[4];
    const float* ec2_s  = (const float*)d_in[5];
    const float* ec2_t  = (const float*)d_in[6];
    const float* ec3_w  = (const float*)d_in[7];
    const float* ec3_s  = (const float*)d_in[8];
    const float* ec3_t  = (const float*)d_in[9];
    const float* ec4_w  = (const float*)d_in[10];
    const float* ec4_s  = (const float*)d_in[11];
    const float* ec4_t  = (const float*)d_in[12];
    const float* fuse_w = (const float*)d_in[13];
    const float* fuse_s = (const float*)d_in[14];
    const float* fuse_t = (const float*)d_in[15];
    const float* emb_w  = (const float*)d_in[16];
    const float* emb_s  = (const float*)d_in[17];
    const float* emb_t  = (const float*)d_in[18];
    const float* h1_w   = (const float*)d_in[19];
    const float* h1_s   = (const float*)d_in[20];
    const float* h1_t   = (const float*)d_in[21];
    const float* h2_w   = (const float*)d_in[22];
    const float* h2_s   = (const float*)d_in[23];
    const float* h2_t   = (const float*)d_in[24];
    const float* h3_w   = (const float*)d_in[25];
    const float* h3_b   = (const float*)d_in[26];
    float* out = (float*)d_out;

    // raise dynamic smem limits (idempotent)
    cudaFuncSetAttribute(gemm_mma<4, 128, true>, cudaFuncAttributeMaxDynamicSharedMemorySize, gsmem(128, true));
    cudaFuncSetAttribute(gemm_mma<0, 128, true>, cudaFuncAttributeMaxDynamicSharedMemorySize, gsmem(128, true));
    cudaFuncSetAttribute(gemm_mma<1, 128, true>, cudaFuncAttributeMaxDynamicSharedMemorySize, gsmem(128, true));
    cudaFuncSetAttribute(gemm_mma<2, 128, true>, cudaFuncAttributeMaxDynamicSharedMemorySize, gsmem(128, true));
    cudaFuncSetAttribute(gemm_mma<0, 64, true>,  cudaFuncAttributeMaxDynamicSharedMemorySize, gsmem(64, true));
    cudaFuncSetAttribute(gemm_mma<0, 64, false>, cudaFuncAttributeMaxDynamicSharedMemorySize, gsmem(64, false));
    cudaFuncSetAttribute(gemm_mma<3, 64, false>, cudaFuncAttributeMaxDynamicSharedMemorySize, gsmem(64, false));

    float *pG, *pxcat, *pYZ, *pxloc, *pxemb, *ph1, *ph2, *pxx, *pglob, *pgb;
    float *pmean, *pmsum;
    __nv_bfloat16 *pXb, *pXb2, *pXc, *pWb;
    int* pidx;
    cudaGetSymbolAddress((void**)&pG, g_G);
    cudaGetSymbolAddress((void**)&pxcat, g_xcat);
    cudaGetSymbolAddress((void**)&pYZ, g_YZ);
    cudaGetSymbolAddress((void**)&pxloc, g_xlocal);
    cudaGetSymbolAddress((void**)&pxemb, g_xemb);
    cudaGetSymbolAddress((void**)&ph1, g_h1);
    cudaGetSymbolAddress((void**)&ph2, g_h2);
    cudaGetSymbolAddress((void**)&pxx, g_xx);
    cudaGetSymbolAddress((void**)&pglob, g_glob);
    cudaGetSymbolAddress((void**)&pgb, g_gbias);
    cudaGetSymbolAddress((void**)&pmean, g_mean);
    cudaGetSymbolAddress((void**)&pmsum, g_msum);
    cudaGetSymbolAddress((void**)&pXb, g_Xb);
    cudaGetSymbolAddress((void**)&pXb2, g_Xb2);
    cudaGetSymbolAddress((void**)&pXc, g_Xc);
    cudaGetSymbolAddress((void**)&pWb, g_Wb);
    cudaGetSymbolAddress((void**)&pidx, g_idx);

    // ---- layer 1: exact fused kNN on xyz; YZ from xyz split (C=3, sync) -----
    conv_split<<<cgrid((long)MTOT * 3), 256>>>(xyz, 3, 3, MTOT, pXc);
    prep_wc_split<<<cgrid(64 * 3), 256>>>(ec1_w, pWb + OFF_EC1, 64, 3);
    gemm_mma<0, 64, false><<<tgrid(MTOT, 128, 1, 64), 256, gsmem(64, false)>>>(
        pXc, 6, 0L, 3, pWb + OFF_EC1, 6, 0L, 3, pYZ, 128, 0L,
        MTOT, 3, 128, nullptr, nullptr, nullptr, nullptr, 0);
    topk_xyz<<<MTOT, 128>>>(xyz, pidx);
    // hoisted weight preps (independent; overlap with layer-1 tail)
    prep_wc_split<<<cgrid(64 * 64), 256>>>(ec2_w, pWb + OFF_EC2, 64, 64);
    prep_wc_split<<<cgrid(128 * 64), 256>>>(ec3_w, pWb + OFF_EC3, 128, 64);
    prep_wc_split<<<cgrid(256 * 128), 256>>>(ec4_w, pWb + OFF_EC4, 256, 128);
    conv_split<<<cgrid(512L * 512), 256>>>(fuse_w, 512, 512, 512, pWb + OFF_FUSE);
    conv_split<<<cgrid(1024L * 512), 256>>>(emb_w, 512, 512, 1024, pWb + OFF_EMB);
    conv_split<<<cgrid(256L * 512), 256>>>(h1_w, 1536, 512, 256, pWb + OFF_H1);
    conv_split<<<cgrid(256L * 256), 256>>>(h2_w, 256, 256, 256, pWb + OFF_H2);
    conv_split<<<cgrid(13L * 256), 256>>>(h3_w, 256, 256, 13, pWb + OFF_H3);
    edge_max_kernel<<<MTOT, 128>>>(pYZ, 128, pidx, ec1_s, ec1_t,
                                   pxcat + 0, 512, pXb + 0, 64);

    // ---- layers 2-4 ----
    run_edge_layer_tc(pxcat + 0,   0,   64,  64,  pWb + OFF_EC2, ec2_s, ec2_t,
                      pG, pxx, pidx, pmean, pmsum, pXb, pXc, pYZ, pxcat + 64, 64);
    run_edge_layer_tc(pxcat + 64,  64,  64,  128, pWb + OFF_EC3, ec3_s, ec3_t,
                      pG, pxx, pidx, pmean, pmsum, pXb, pXc, pYZ, pxcat + 128, 128);
    run_edge_layer_tc(pxcat + 128, 128, 128, 256, pWb + OFF_EC4, ec4_s, ec4_t,
                      pG, pxx, pidx, pmean, pmsum, pXb, pXc, pYZ, pxcat + 256, 256);

    // fuse: (16384,512) -> 512, lrelu; split output fused into epilogue
    gemm_mma<1, 128, true><<<tgrid(MTOT, 512, 1, 128), 256, gsmem(128, true)>>>(
        pXb, 1024, 0L, 512, pWb + OFF_FUSE, 1024, 0L, 512, pxloc, 512, 0L,
        MTOT, 512, 512, fuse_s, fuse_t, nullptr, pXb2, 1024);
    // emb: 512 -> 1024, lrelu
    gemm_mma<1, 128, true><<<tgrid(MTOT, 1024, 1, 128), 256, gsmem(128, true)>>>(
        pXb2, 1024, 0L, 512, pWb + OFF_EMB, 1024, 0L, 512, pxemb, 1024, 0L,
        MTOT, 512, 1024, emb_s, emb_t, nullptr, nullptr, 0);
    // global max over N + per-batch bias via h1_w[:,512:]
    maxreduce_kernel<<<dim3(32, BATCH), 256>>>(pxemb, pglob);
    gbias_kernel<<<BATCH, 256>>>(h1_w, pglob, pgb);
    // h1: 512 -> 256 with per-batch gadd, lrelu; split out -> pXb
    gemm_mma<2, 128, true><<<tgrid(MTOT, 256, 1, 128), 256, gsmem(128, true)>>>(
        pXb2, 1024, 0L, 512, pWb + OFF_H1, 1024, 0L, 512, ph1, 256, 0L,
        MTOT, 512, 256, h1_s, h1_t, pgb, pXb, 512);
    // h2: 256 -> 256, lrelu; split out -> pXb2
    gemm_mma<1, 128, true><<<tgrid(MTOT, 256, 1, 128), 256, gsmem(128, true)>>>(
        pXb, 512, 0L, 256, pWb + OFF_H2, 512, 0L, 256, ph2, 256, 0L,
        MTOT, 256, 256, h2_s, h2_t, nullptr, pXb2, 512);
    // h3: 256 -> 13, +bias -> d_out (sync path, O=13)
    gemm_mma<3, 64, false><<<tgrid(MTOT, 13, 1, 64), 256, gsmem(64, false)>>>(
        pXb2, 512, 0L, 256, pWb + OFF_H3, 512, 0L, 256, out, 13, 0L,
        MTOT, 256, 13, nullptr, h3_b, nullptr, nullptr, 0);
}